// round 12
// baseline (speedup 1.0000x reference)
#include <cuda_runtime.h>
#include <cuda_fp16.h>
#include <cstdint>
#include <math.h>

// ---------------------------------------------------------------------------
// Mamba block forward. GEMMs via mma.sync HMMA fp16 single-pass (fp32 accum).
// CTA 128x128, 4 warps x (64x64) warp tiles (smem-traffic optimized),
// 3-stage cp.async, 2 CTAs/SM. All intermediates fp16.
// ---------------------------------------------------------------------------

#define BATCH   2
#define SEQ     1024
#define DMODEL  1024
#define DINNER  2048
#define DSTATE  16
#define DTRANK  64
#define DCONV   4
#define NTOK    (BATCH * SEQ)
#define XPROJ_N (DTRANK + 2 * DSTATE)   // 96
#define XSPLIT  16

typedef __half f16;

// fp32 scratch
__device__ __align__(256) float g_bcT[2 * DSTATE * NTOK];
__device__ __align__(256) float g_part[XSPLIT * NTOK * XPROJ_N];

// fp16 weights + activations
__device__ __align__(256) f16 g_wi[2 * DINNER * DMODEL];
__device__ __align__(256) f16 g_wx[XPROJ_N * DINNER];
__device__ __align__(256) f16 g_wd[DINNER * DTRANK];
__device__ __align__(256) f16 g_wo[DMODEL * DINNER];
__device__ __align__(256) f16 g_hh[NTOK * DMODEL];
__device__ __align__(256) f16 g_xz[NTOK * 2 * DINNER];
__device__ __align__(256) f16 g_xsh[NTOK * DINNER];
__device__ __align__(256) f16 g_xsT[DINNER * NTOK];
__device__ __align__(256) f16 g_gT[DINNER * NTOK];
__device__ __align__(256) f16 g_dtT[DINNER * NTOK];
__device__ __align__(256) f16 g_yT[DINNER * NTOK];
__device__ __align__(256) f16 g_xdh[NTOK * XPROJ_N];
__device__ __align__(256) f16 g_yh[NTOK * DINNER];

// ---------------------------------------------------------------------------
// helpers
// ---------------------------------------------------------------------------
__device__ __forceinline__ uint32_t smem_u32(const void* p) {
    uint32_t a;
    asm("{ .reg .u64 t; cvta.to.shared.u64 t, %1; cvt.u32.u64 %0, t; }"
        : "=r"(a) : "l"(p));
    return a;
}
__device__ __forceinline__ void ldm_x4(uint32_t& r0, uint32_t& r1,
                                       uint32_t& r2, uint32_t& r3, uint32_t a) {
    asm volatile("ldmatrix.sync.aligned.m8n8.x4.shared.b16 {%0,%1,%2,%3}, [%4];"
                 : "=r"(r0), "=r"(r1), "=r"(r2), "=r"(r3) : "r"(a));
}
__device__ __forceinline__ void mma16816(float* d, const uint32_t* a,
                                         const uint32_t* b) {
    asm volatile(
        "mma.sync.aligned.m16n8k16.row.col.f32.f16.f16.f32 "
        "{%0,%1,%2,%3}, {%4,%5,%6,%7}, {%8,%9}, {%0,%1,%2,%3};"
        : "+f"(d[0]), "+f"(d[1]), "+f"(d[2]), "+f"(d[3])
        : "r"(a[0]), "r"(a[1]), "r"(a[2]), "r"(a[3]), "r"(b[0]), "r"(b[1]));
}
__device__ __forceinline__ void cp16(uint32_t dst, const void* src, int sz) {
    asm volatile("cp.async.cg.shared.global [%0], [%1], 16, %2;"
                 :: "r"(dst), "l"(src), "r"(sz) : "memory");
}
#define CP_COMMIT() asm volatile("cp.async.commit_group;" ::: "memory")
#define CP_WAIT(n)  asm volatile("cp.async.wait_group %0;" :: "n"(n) : "memory")

__device__ __forceinline__ uint32_t pack2(f16 a, f16 b) {
    return ((uint32_t)__half_as_ushort(b) << 16) | __half_as_ushort(a);
}
__device__ __forceinline__ uint2 cvt4(float4 v) {
    uint2 r;
    r.x = pack2(__float2half_rn(v.x), __float2half_rn(v.y));
    r.y = pack2(__float2half_rn(v.z), __float2half_rn(v.w));
    return r;
}
__device__ __forceinline__ void unpack4(uint2 u, float* f) {
    __half2 a = *reinterpret_cast<__half2*>(&u.x);
    __half2 b = *reinterpret_cast<__half2*>(&u.y);
    float2 fa = __half22float2(a), fb = __half22float2(b);
    f[0] = fa.x; f[1] = fa.y; f[2] = fb.x; f[3] = fb.y;
}
__device__ __forceinline__ float softplus_f(float v) {
    return (v > 15.f) ? v : log1pf(__expf(v));
}
__device__ __forceinline__ float silu_f(float v) {
    return v / (1.f + __expf(-v));
}

// ---------------------------------------------------------------------------
// HMMA GEMM (NT): C[M,N] = A[M,K]·B[N,K]^T, fp16 x fp16 -> fp32 accum.
// CTA 128x128, 4 warps of 64x64, 128 threads, K-chunk 64, 3-stage cp.async,
// 2 CTAs/SM (=> 8 warps/SM). smem traffic per FLOP reduced 33% vs 8x(64x32).
// EPI: 0 none, 1 softplus(acc+bias[n]), 2 acc+res[m,n] (fp32 out).
// TRANS: transposed fp16 store.  HOUT: 1 fp16 out, else fp32 (+split-K).
// ---------------------------------------------------------------------------
#define STAGE_SZ 32768
#define NSTAGE 3
#define GEMM_SMEM (NSTAGE * STAGE_SZ)   // 96 KB
#define GTHREADS 128

template<int EPI, int TRANS, int HOUT>
__global__ void __launch_bounds__(GTHREADS, 2) mma_gemm(
    const f16* __restrict__ A, int lda,
    const f16* __restrict__ B, int ldb,
    void* __restrict__ Cv, int ldc, int N, int Ksplit, long partStride,
    const float* __restrict__ bias,
    const float* __restrict__ res, int ldres)
{
    extern __shared__ char smem[];
    const uint32_t sb = smem_u32(smem);
    const int tid = threadIdx.x;
    const int bRow = blockIdx.y * 128, bCol = blockIdx.x * 128;
    const int kbase = blockIdx.z * Ksplit;
    const int nChunks = Ksplit >> 6;

    const int wid = tid >> 5, l = tid & 31;
    const int wm = (wid & 1) * 64, wn = (wid >> 1) * 64;

    float acc[4][8][4];
    #pragma unroll
    for (int a = 0; a < 4; a++)
        #pragma unroll
        for (int b = 0; b < 8; b++)
            #pragma unroll
            for (int c = 0; c < 4; c++) acc[a][b][c] = 0.f;

    auto loadStage = [&](int c) {
        const int kt = kbase + (c << 6);
        const uint32_t base = sb + (c % NSTAGE) * STAGE_SZ;
        #pragma unroll
        for (int it = 0; it < 8; it++) {
            int lin = it * GTHREADS + tid;     // 0..1023
            int row = lin >> 3, ch = lin & 7;
            uint32_t d = base + row * 128 + (((ch ^ (row & 7)) << 4));
            size_t aoff = (size_t)(bRow + row) * lda + kt + ch * 8;
            cp16(d, A + aoff, 16);
            int bn = bCol + row;
            int ok = (bn < N) ? 16 : 0;
            size_t boff = (size_t)(bn < N ? bn : 0) * ldb + kt + ch * 8;
            cp16(d + 16384, B + boff, ok);
        }
        CP_COMMIT();
    };

    loadStage(0);
    if (nChunks > 1) loadStage(1);
    for (int c = 0; c < nChunks; c++) {
        if (c + 2 < nChunks) { loadStage(c + 2); CP_WAIT(2); }
        else if (c + 1 < nChunks) { CP_WAIT(1); }
        else { CP_WAIT(0); }
        __syncthreads();
        const uint32_t st = sb + (c % NSTAGE) * STAGE_SZ;

        const int hkA = l >> 4;
        const int matb = l >> 3;
        const int rB0 = wn + (l & 7) + ((matb >> 1) << 3);
        const int hkB = matb & 1;

        #pragma unroll
        for (int ks = 0; ks < 4; ks++) {
            uint32_t Af[4][4], Bf[8][2];
            #pragma unroll
            for (int mi = 0; mi < 4; mi++) {
                int r = wm + mi * 16 + (l & 15);
                int ck = 2 * ks + hkA;
                uint32_t ad = st + r * 128 + ((ck ^ (r & 7)) << 4);
                ldm_x4(Af[mi][0], Af[mi][1], Af[mi][2], Af[mi][3], ad);
            }
            #pragma unroll
            for (int ng = 0; ng < 4; ng++) {
                int r = rB0 + ng * 16;
                int ck = 2 * ks + hkB;
                uint32_t ad = st + 16384 + r * 128 + ((ck ^ (r & 7)) << 4);
                uint32_t t0, t1, t2, t3;
                ldm_x4(t0, t1, t2, t3, ad);
                Bf[ng*2][0] = t0; Bf[ng*2][1] = t1;
                Bf[ng*2+1][0] = t2; Bf[ng*2+1][1] = t3;
            }
            #pragma unroll
            for (int mi = 0; mi < 4; mi++)
                #pragma unroll
                for (int ni = 0; ni < 8; ni++)
                    mma16816(acc[mi][ni], Af[mi], Bf[ni]);
        }
        __syncthreads();
    }

    if (TRANS) {
        float* ts = reinterpret_cast<float*>(smem);   // [128][132]
        #pragma unroll
        for (int mi = 0; mi < 4; mi++) {
            #pragma unroll
            for (int h2 = 0; h2 < 2; h2++) {
                int row = wm + mi * 16 + h2 * 8 + (l >> 2);
                #pragma unroll
                for (int ni = 0; ni < 8; ni++) {
                    int col = wn + ni * 8 + (l & 3) * 2;
                    float v0 = acc[mi][ni][h2 * 2 + 0];
                    float v1 = acc[mi][ni][h2 * 2 + 1];
                    if (EPI == 1) {
                        v0 = softplus_f(v0 + bias[bCol + col]);
                        v1 = softplus_f(v1 + bias[bCol + col + 1]);
                    }
                    ts[(col) * 132 + row] = v0;
                    ts[(col + 1) * 132 + row] = v1;
                }
            }
        }
        __syncthreads();
        f16* Ch = reinterpret_cast<f16*>(Cv);
        #pragma unroll
        for (int i = 0; i < 64; i++) {
            int idx = i * GTHREADS + tid;       // 8192 half2 stores
            int r = idx >> 6, c2 = (idx & 63) * 2;
            uint v = pack2(__float2half_rn(ts[r * 132 + c2]),
                           __float2half_rn(ts[r * 132 + c2 + 1]));
            *reinterpret_cast<uint*>(Ch + (size_t)(bCol + r) * ldc + bRow + c2) = v;
        }
    } else {
        #pragma unroll
        for (int mi = 0; mi < 4; mi++) {
            #pragma unroll
            for (int h2 = 0; h2 < 2; h2++) {
                int row = bRow + wm + mi * 16 + h2 * 8 + (l >> 2);
                #pragma unroll
                for (int ni = 0; ni < 8; ni++) {
                    int col = bCol + wn + ni * 8 + (l & 3) * 2;
                    if (col < N) {
                        float v0 = acc[mi][ni][h2 * 2 + 0];
                        float v1 = acc[mi][ni][h2 * 2 + 1];
                        if (EPI == 1) {
                            v0 = softplus_f(v0 + bias[col]);
                            v1 = softplus_f(v1 + bias[col + 1]);
                        } else if (EPI == 2) {
                            const float* rr = res + (size_t)row * ldres + col;
                            v0 += rr[0]; v1 += rr[1];
                        }
                        if (HOUT) {
                            f16* Ch = reinterpret_cast<f16*>(Cv);
                            *reinterpret_cast<uint*>(
                                Ch + (size_t)row * ldc + col) =
                                pack2(__float2half_rn(v0), __float2half_rn(v1));
                        } else {
                            float* Cf = reinterpret_cast<float*>(Cv) +
                                        (long)blockIdx.z * partStride;
                            *reinterpret_cast<float2*>(
                                Cf + (size_t)row * ldc + col) =
                                make_float2(v0, v1);
                        }
                    }
                }
            }
        }
    }
}

// ---------------------------------------------------------------------------
// all weights fp32 -> fp16 in one launch
// ---------------------------------------------------------------------------
#define NW0 (2 * DINNER * DMODEL / 4)
#define NW1 (XPROJ_N * DINNER / 4)
#define NW2 (DINNER * DTRANK / 4)
#define NW3 (DMODEL * DINNER / 4)
#define NWTOT (NW0 + NW1 + NW2 + NW3)

__global__ __launch_bounds__(256) void convert_all(
    const float* __restrict__ w0, f16* __restrict__ o0,
    const float* __restrict__ w1, f16* __restrict__ o1,
    const float* __restrict__ w2, f16* __restrict__ o2,
    const float* __restrict__ w3, f16* __restrict__ o3)
{
    int i = blockIdx.x * 256 + threadIdx.x;
    const float* w; f16* o; int j;
    if (i < NW0)                  { w = w0; o = o0; j = i; }
    else if (i < NW0 + NW1)       { w = w1; o = o1; j = i - NW0; }
    else if (i < NW0 + NW1 + NW2) { w = w2; o = o2; j = i - NW0 - NW1; }
    else if (i < NWTOT)           { w = w3; o = o3; j = i - NW0 - NW1 - NW2; }
    else return;
    float4 v = reinterpret_cast<const float4*>(w)[j];
    reinterpret_cast<uint2*>(o)[j] = cvt4(v);
}

// ---------------------------------------------------------------------------
// RMSNorm -> fp16
// ---------------------------------------------------------------------------
__global__ __launch_bounds__(256) void rmsnorm_kernel(
    const float* __restrict__ x, const float* __restrict__ w,
    f16* __restrict__ hh)
{
    int row = blockIdx.x;
    int tid = threadIdx.x;
    float4 v = reinterpret_cast<const float4*>(x + (size_t)row * DMODEL)[tid];
    float ss = v.x * v.x + v.y * v.y + v.z * v.z + v.w * v.w;
    __shared__ float red[8];
    #pragma unroll
    for (int o = 16; o > 0; o >>= 1) ss += __shfl_xor_sync(0xffffffffu, ss, o);
    if ((tid & 31) == 0) red[tid >> 5] = ss;
    __syncthreads();
    if (tid < 32) {
        float t = (tid < 8) ? red[tid] : 0.f;
        #pragma unroll
        for (int o = 4; o > 0; o >>= 1) t += __shfl_xor_sync(0xffffffffu, t, o);
        if (tid == 0) red[0] = t;
    }
    __syncthreads();
    float scale = rsqrtf(red[0] * (1.0f / DMODEL) + 1e-5f);
    float4 wv = reinterpret_cast<const float4*>(w)[tid];
    float4 o;
    o.x = v.x * scale * wv.x;  o.y = v.y * scale * wv.y;
    o.z = v.z * scale * wv.z;  o.w = v.w * scale * wv.w;
    reinterpret_cast<uint2*>(hh + (size_t)row * DMODEL)[tid] = cvt4(o);
}

// ---------------------------------------------------------------------------
// Tiled conv(width4)+SiLU + silu(z), half2-vectorized, packed smem.
// ---------------------------------------------------------------------------
#define CT 32
#define CD 64

__global__ __launch_bounds__(256) void conv_silu_kernel(
    const f16* __restrict__ xz,
    const float* __restrict__ conv_w, const float* __restrict__ conv_b,
    f16* __restrict__ xsh, f16* __restrict__ xsT, f16* __restrict__ gT)
{
    __shared__ uint xc2[CT + 3][CD / 2];
    __shared__ uint sxu[CD / 2][CT + 1];
    __shared__ uint sgu[CD / 2][CT + 1];

    const int tid = threadIdx.x;
    const int d0 = blockIdx.x * CD;
    const int t0 = blockIdx.y * CT;
    const bool halo = (t0 & (SEQ - 1)) != 0;

    #pragma unroll
    for (int it = 0; it < 5; it++) {
        int lin = it * 256 + tid;
        if (lin < (CT + 3) * (CD / 2)) {
            int i = lin >> 5, c2 = lin & 31;
            uint v = 0;
            if (i >= 3 || halo)
                v = *reinterpret_cast<const uint*>(
                    xz + (size_t)(t0 - 3 + i) * (2 * DINNER) + d0 + c2 * 2);
            xc2[i][c2] = v;
        }
    }
    __syncthreads();

    #pragma unroll
    for (int it = 0; it < 4; it++) {
        int lin = it * 256 + tid;
        int tok = lin >> 5, c2 = lin & 31;
        int d = d0 + c2 * 2;
        float2 a = *reinterpret_cast<const float2*>(conv_b + d);
        #pragma unroll
        for (int k = 0; k < DCONV; k++) {
            uint xu = xc2[tok + k][c2];
            float2 xf = __half22float2(*reinterpret_cast<__half2*>(&xu));
            a.x = fmaf(conv_w[d * DCONV + k],       xf.x, a.x);
            a.y = fmaf(conv_w[(d + 1) * DCONV + k], xf.y, a.y);
        }
        uint zu = *reinterpret_cast<const uint*>(
            xz + (size_t)(t0 + tok) * (2 * DINNER) + DINNER + d);
        float2 zf = __half22float2(*reinterpret_cast<__half2*>(&zu));
        uint xsp = pack2(__float2half_rn(silu_f(a.x)),
                         __float2half_rn(silu_f(a.y)));
        *reinterpret_cast<uint*>(xsh + (size_t)(t0 + tok) * DINNER + d) = xsp;
        sxu[c2][tok] = xsp;
        sgu[c2][tok] = pack2(__float2half_rn(silu_f(zf.x)),
                             __float2half_rn(silu_f(zf.y)));
    }
    __syncthreads();

    #pragma unroll
    for (int it = 0; it < 4; it++) {
        int lin = it * 256 + tid;
        int ch = lin >> 4, tp = (lin & 15) * 2;
        int r = ch >> 1;
        uint sel = (ch & 1) ? 0x7632u : 0x5410u;
        uint xa = sxu[r][tp], xb = sxu[r][tp + 1];
        uint ga = sgu[r][tp], gb = sgu[r][tp + 1];
        size_t o = (size_t)(d0 + ch) * NTOK + t0 + tp;
        *reinterpret_cast<uint*>(xsT + o) = __byte_perm(xa, xb, sel);
        *reinterpret_cast<uint*>(gT + o)  = __byte_perm(ga, gb, sel);
    }
}

// ---------------------------------------------------------------------------
// split-K reduce for x_proj
// ---------------------------------------------------------------------------
__global__ __launch_bounds__(256) void reduce_xproj(
    const float* __restrict__ part,
    f16* __restrict__ xdh,
    float* __restrict__ bcT)
{
    int idx = blockIdx.x * 256 + threadIdx.x;
    if (idx >= NTOK * XPROJ_N) return;
    float s = 0.f;
    #pragma unroll
    for (int z = 0; z < XSPLIT; z++) s += part[(size_t)z * NTOK * XPROJ_N + idx];
    xdh[idx] = __float2half_rn(s);
    int row = idx / XPROJ_N, col = idx - row * XPROJ_N;
    if (col >= DTRANK)
        bcT[(size_t)(col - DTRANK) * NTOK + row] = s;
}

// ---------------------------------------------------------------------------
// selective scan + gate
// ---------------------------------------------------------------------------
__global__ __launch_bounds__(256) void scan_kernel(
    const f16* __restrict__ dtT, const f16* __restrict__ xsT,
    const float* __restrict__ bcT, const f16* __restrict__ gT,
    const float* __restrict__ A_log, const float* __restrict__ Dp,
    f16* __restrict__ yT)
{
    int warp = threadIdx.x >> 5;
    int lane = threadIdx.x & 31;
    int chPair = blockIdx.x * 8 + warp;
    int ch = chPair * 2 + (lane >> 4);
    int b = ch >> 11;
    int d = ch & 2047;
    int n = lane & 15;
    int rowBase = b * SEQ;

    const f16* dtp = dtT + (size_t)d * NTOK + rowBase;
    const f16* xsp = xsT + (size_t)d * NTOK + rowBase;
    const f16* gp  = gT  + (size_t)d * NTOK + rowBase;
    const float* Bp = bcT + (size_t)n * NTOK + rowBase;
    const float* Cp = bcT + (size_t)(DSTATE + n) * NTOK + rowBase;
    f16* yp = yT + (size_t)d * NTOK + rowBase;

    float a  = -expf(A_log[d * DSTATE + n]);
    float Dv = Dp[d];
    float s = 0.f;

    uint2 dtu = *reinterpret_cast<const uint2*>(dtp);
    uint2 xsu = *reinterpret_cast<const uint2*>(xsp);
    uint2 gu  = *reinterpret_cast<const uint2*>(gp);
    float4 B4 = *reinterpret_cast<const float4*>(Bp);
    float4 C4 = *reinterpret_cast<const float4*>(Cp);

    for (int t = 0; t < SEQ; t += 4) {
        uint2 ndt, nxs, ng; float4 nB, nC;
        if (t + 4 < SEQ) {
            ndt = *reinterpret_cast<const uint2*>(dtp + t + 4);
            nxs = *reinterpret_cast<const uint2*>(xsp + t + 4);
            ng  = *reinterpret_cast<const uint2*>(gp + t + 4);
            nB  = *reinterpret_cast<const float4*>(Bp + t + 4);
            nC  = *reinterpret_cast<const float4*>(Cp + t + 4);
        }
        float dtv[4], xsv[4], gv[4];
        unpack4(dtu, dtv); unpack4(xsu, xsv); unpack4(gu, gv);
        const float* Bv = &B4.x; const float* Cv = &C4.x;
        float yv[4];
        #pragma unroll
        for (int q = 0; q < 4; q++) {
            float dA = __expf(dtv[q] * a);
            s = fmaf(dA, s, dtv[q] * xsv[q] * Bv[q]);
            float p = s * Cv[q];
            p += __shfl_xor_sync(0xffffffffu, p, 8);
            p += __shfl_xor_sync(0xffffffffu, p, 4);
            p += __shfl_xor_sync(0xffffffffu, p, 2);
            p += __shfl_xor_sync(0xffffffffu, p, 1);
            yv[q] = (p + Dv * xsv[q]) * gv[q];
        }
        if (n == 0) {
            uint2 yo;
            yo.x = pack2(__float2half_rn(yv[0]), __float2half_rn(yv[1]));
            yo.y = pack2(__float2half_rn(yv[2]), __float2half_rn(yv[3]));
            *reinterpret_cast<uint2*>(yp + t) = yo;
        }
        dtu = ndt; xsu = nxs; gu = ng; B4 = nB; C4 = nC;
    }
}

// ---------------------------------------------------------------------------
// yT fp16 [DINNER][NTOK] -> y fp16 [NTOK][DINNER]
// ---------------------------------------------------------------------------
__global__ __launch_bounds__(256) void transpose_y(
    const f16* __restrict__ yT, f16* __restrict__ yh)
{
    __shared__ f16 tile[64][34];
    int bx = blockIdx.x, by = blockIdx.y;
    #pragma unroll
    for (int it = 0; it < 4; it++) {
        int lin = it * 256 + threadIdx.x;
        int dd = lin >> 4, t2 = (lin & 15) * 2;
        uint v = *reinterpret_cast<const uint*>(
            yT + (size_t)(by * 64 + dd) * NTOK + bx * 32 + t2);
        __half2 h = *reinterpret_cast<__half2*>(&v);
        tile[dd][t2] = __low2half(h);
        tile[dd][t2 + 1] = __high2half(h);
    }
    __syncthreads();
    #pragma unroll
    for (int it = 0; it < 4; it++) {
        int lin = it * 256 + threadIdx.x;
        int tok = lin >> 5, d2 = (lin & 31) * 2;
        uint v = pack2(tile[d2][tok], tile[d2 + 1][tok]);
        *reinterpret_cast<uint*>(
            yh + (size_t)(bx * 32 + tok) * DINNER + by * 64 + d2) = v;
    }
}

// ---------------------------------------------------------------------------
// Launch
// ---------------------------------------------------------------------------
extern "C" void kernel_launch(void* const* d_in, const int* in_sizes, int n_in,
                              void* d_out, int out_size)
{
    const float* x         = (const float*)d_in[0];
    const float* norm_w    = (const float*)d_in[1];
    const float* in_proj_w = (const float*)d_in[2];
    const float* conv_w    = (const float*)d_in[3];
    const float* conv_b    = (const float*)d_in[4];
    const float* x_proj_w  = (const float*)d_in[5];
    const float* dt_proj_w = (const float*)d_in[6];
    const float* dt_proj_b = (const float*)d_in[7];
    const float* A_log     = (const float*)d_in[8];
    const float* Dp        = (const float*)d_in[9];
    const float* out_proj_w= (const float*)d_in[10];
    float* out = (float*)d_out;

    float *pbcT, *ppart;
    f16 *pwi, *pwx, *pwd, *pwo, *phh, *pxz, *pxsh, *pxsT, *pgT, *pdtT, *pyT,
        *pxdh, *pyh;
    cudaGetSymbolAddress((void**)&pbcT, g_bcT);
    cudaGetSymbolAddress((void**)&ppart,g_part);
    cudaGetSymbolAddress((void**)&pwi,  g_wi);
    cudaGetSymbolAddress((void**)&pwx,  g_wx);
    cudaGetSymbolAddress((void**)&pwd,  g_wd);
    cudaGetSymbolAddress((void**)&pwo,  g_wo);
    cudaGetSymbolAddress((void**)&phh,  g_hh);
    cudaGetSymbolAddress((void**)&pxz,  g_xz);
    cudaGetSymbolAddress((void**)&pxsh, g_xsh);
    cudaGetSymbolAddress((void**)&pxsT, g_xsT);
    cudaGetSymbolAddress((void**)&pgT,  g_gT);
    cudaGetSymbolAddress((void**)&pdtT, g_dtT);
    cudaGetSymbolAddress((void**)&pyT,  g_yT);
    cudaGetSymbolAddress((void**)&pxdh, g_xdh);
    cudaGetSymbolAddress((void**)&pyh,  g_yh);

    cudaFuncSetAttribute(mma_gemm<0,0,0>, cudaFuncAttributeMaxDynamicSharedMemorySize, GEMM_SMEM);
    cudaFuncSetAttribute(mma_gemm<0,0,1>, cudaFuncAttributeMaxDynamicSharedMemorySize, GEMM_SMEM);
    cudaFuncSetAttribute(mma_gemm<1,1,1>, cudaFuncAttributeMaxDynamicSharedMemorySize, GEMM_SMEM);
    cudaFuncSetAttribute(mma_gemm<2,0,0>, cudaFuncAttributeMaxDynamicSharedMemorySize, GEMM_SMEM);

    // 0) all weight conversions in one launch
    convert_all<<<(NWTOT + 255) / 256, 256>>>(
        in_proj_w, pwi, x_proj_w, pwx, dt_proj_w, pwd, out_proj_w, pwo);

    // 1) RMSNorm
    rmsnorm_kernel<<<NTOK, 256>>>(x, norm_w, phh);

    // 2) in_proj -> xz fp16
    {
        dim3 grid((2 * DINNER) / 128, NTOK / 128, 1);
        mma_gemm<0,0,1><<<grid, GTHREADS, GEMM_SMEM>>>(
            phh, DMODEL, pwi, DMODEL,
            pxz, 2 * DINNER, 2 * DINNER, DMODEL, 0, nullptr, nullptr, 0);
    }

    // 3) conv + silu
    {
        dim3 grid(DINNER / CD, NTOK / CT);
        conv_silu_kernel<<<grid, 256>>>(pxz, conv_w, conv_b,
                                        pxsh, pxsT, pgT);
    }

    // 4) x_proj split-K -> fp32 partials
    {
        dim3 grid(1, NTOK / 128, XSPLIT);
        mma_gemm<0,0,0><<<grid, GTHREADS, GEMM_SMEM>>>(
            pxsh, DINNER, pwx, DINNER,
            ppart, XPROJ_N, XPROJ_N, DINNER / XSPLIT,
            (long)NTOK * XPROJ_N, nullptr, nullptr, 0);
    }
    reduce_xproj<<<(NTOK * XPROJ_N + 255) / 256, 256>>>(ppart, pxdh, pbcT);

    // 5) dt_proj + softplus -> dtT fp16
    {
        dim3 grid(DINNER / 128, NTOK / 128, 1);
        mma_gemm<1,1,1><<<grid, GTHREADS, GEMM_SMEM>>>(
            pxdh, XPROJ_N, pwd, DTRANK,
            pdtT, NTOK, DINNER, DTRANK, 0, dt_proj_b, nullptr, 0);
    }

    // 6) scan -> yT fp16
    scan_kernel<<<(BATCH * DINNER) / 16, 256>>>(pdtT, pxsT, pbcT, pgT,
                                                A_log, Dp, pyT);

    // 7) transpose y
    {
        dim3 grid(NTOK / 32, DINNER / 64);
        transpose_y<<<grid, 256>>>(pyT, pyh);
    }

    // 8) out_proj + residual (direct, fused epilogue)
    {
        dim3 grid(DMODEL / 128, NTOK / 128, 1);
        mma_gemm<2,0,0><<<grid, GTHREADS, GEMM_SMEM>>>(
            pyh, DINNER, pwo, DINNER,
            out, DMODEL, DMODEL, DINNER, 0, nullptr, x, DMODEL);
    }
}

// round 13
// speedup vs baseline: 1.0548x; 1.0548x over previous
#include <cuda_runtime.h>
#include <cuda_fp16.h>
#include <cstdint>
#include <math.h>

// ---------------------------------------------------------------------------
// Mamba block forward. GEMMs via mma.sync HMMA fp16 single-pass (fp32 accum).
// 128x128 CTA tiles, 8 warps (64x32), 3-stage cp.async, 2 CTAs/SM,
// single-barrier-per-chunk pipeline. All intermediates fp16.
// ---------------------------------------------------------------------------

#define BATCH   2
#define SEQ     1024
#define DMODEL  1024
#define DINNER  2048
#define DSTATE  16
#define DTRANK  64
#define DCONV   4
#define NTOK    (BATCH * SEQ)
#define XPROJ_N (DTRANK + 2 * DSTATE)   // 96
#define XSPLIT  16

typedef __half f16;

// fp32 scratch
__device__ __align__(256) float g_bcT[2 * DSTATE * NTOK];
__device__ __align__(256) float g_part[XSPLIT * NTOK * XPROJ_N];

// fp16 weights + activations
__device__ __align__(256) f16 g_wi[2 * DINNER * DMODEL];
__device__ __align__(256) f16 g_wx[XPROJ_N * DINNER];
__device__ __align__(256) f16 g_wd[DINNER * DTRANK];
__device__ __align__(256) f16 g_wo[DMODEL * DINNER];
__device__ __align__(256) f16 g_hh[NTOK * DMODEL];
__device__ __align__(256) f16 g_xz[NTOK * 2 * DINNER];
__device__ __align__(256) f16 g_xsh[NTOK * DINNER];
__device__ __align__(256) f16 g_xsT[DINNER * NTOK];
__device__ __align__(256) f16 g_gT[DINNER * NTOK];
__device__ __align__(256) f16 g_dtT[DINNER * NTOK];
__device__ __align__(256) f16 g_yT[DINNER * NTOK];
__device__ __align__(256) f16 g_xdh[NTOK * XPROJ_N];
__device__ __align__(256) f16 g_yh[NTOK * DINNER];

// ---------------------------------------------------------------------------
// helpers
// ---------------------------------------------------------------------------
__device__ __forceinline__ uint32_t smem_u32(const void* p) {
    uint32_t a;
    asm("{ .reg .u64 t; cvta.to.shared.u64 t, %1; cvt.u32.u64 %0, t; }"
        : "=r"(a) : "l"(p));
    return a;
}
__device__ __forceinline__ void ldm_x4(uint32_t& r0, uint32_t& r1,
                                       uint32_t& r2, uint32_t& r3, uint32_t a) {
    asm volatile("ldmatrix.sync.aligned.m8n8.x4.shared.b16 {%0,%1,%2,%3}, [%4];"
                 : "=r"(r0), "=r"(r1), "=r"(r2), "=r"(r3) : "r"(a));
}
__device__ __forceinline__ void mma16816(float* d, const uint32_t* a,
                                         const uint32_t* b) {
    asm volatile(
        "mma.sync.aligned.m16n8k16.row.col.f32.f16.f16.f32 "
        "{%0,%1,%2,%3}, {%4,%5,%6,%7}, {%8,%9}, {%0,%1,%2,%3};"
        : "+f"(d[0]), "+f"(d[1]), "+f"(d[2]), "+f"(d[3])
        : "r"(a[0]), "r"(a[1]), "r"(a[2]), "r"(a[3]), "r"(b[0]), "r"(b[1]));
}
__device__ __forceinline__ void cp16(uint32_t dst, const void* src, int sz) {
    asm volatile("cp.async.cg.shared.global [%0], [%1], 16, %2;"
                 :: "r"(dst), "l"(src), "r"(sz) : "memory");
}
#define CP_COMMIT() asm volatile("cp.async.commit_group;" ::: "memory")
#define CP_WAIT(n)  asm volatile("cp.async.wait_group %0;" :: "n"(n) : "memory")

__device__ __forceinline__ uint32_t pack2(f16 a, f16 b) {
    return ((uint32_t)__half_as_ushort(b) << 16) | __half_as_ushort(a);
}
__device__ __forceinline__ uint2 cvt4(float4 v) {
    uint2 r;
    r.x = pack2(__float2half_rn(v.x), __float2half_rn(v.y));
    r.y = pack2(__float2half_rn(v.z), __float2half_rn(v.w));
    return r;
}
__device__ __forceinline__ void unpack4(uint2 u, float* f) {
    __half2 a = *reinterpret_cast<__half2*>(&u.x);
    __half2 b = *reinterpret_cast<__half2*>(&u.y);
    float2 fa = __half22float2(a), fb = __half22float2(b);
    f[0] = fa.x; f[1] = fa.y; f[2] = fb.x; f[3] = fb.y;
}
__device__ __forceinline__ float softplus_f(float v) {
    return (v > 15.f) ? v : log1pf(__expf(v));
}
__device__ __forceinline__ float silu_f(float v) {
    return v / (1.f + __expf(-v));
}

// ---------------------------------------------------------------------------
// HMMA GEMM (NT): C[M,N] = A[M,K]·B[N,K]^T, fp16 x fp16 -> fp32 accum.
// CTA 128x128, 8 warps (64x32), K-chunk 64, 3-stage cp.async, 2 CTAs/SM.
// ONE __syncthreads per chunk (loadStage issued post-barrier).
// EPI: 0 none, 1 softplus(acc+bias[n]), 2 acc+res[m,n] (fp32 out).
// TRANS: transposed fp16 store.  HOUT: 1 fp16 out, else fp32 (+split-K).
// ---------------------------------------------------------------------------
#define STAGE_SZ 32768
#define NSTAGE 3
#define GEMM_SMEM (NSTAGE * STAGE_SZ)   // 96 KB

template<int EPI, int TRANS, int HOUT>
__global__ void __launch_bounds__(256, 2) mma_gemm(
    const f16* __restrict__ A, int lda,
    const f16* __restrict__ B, int ldb,
    void* __restrict__ Cv, int ldc, int N, int Ksplit, long partStride,
    const float* __restrict__ bias,
    const float* __restrict__ res, int ldres)
{
    extern __shared__ char smem[];
    const uint32_t sb = smem_u32(smem);
    const int tid = threadIdx.x;
    const int bRow = blockIdx.y * 128, bCol = blockIdx.x * 128;
    const int kbase = blockIdx.z * Ksplit;
    const int nChunks = Ksplit >> 6;

    const int wid = tid >> 5, l = tid & 31;
    const int wm = (wid >> 2) * 64, wn = (wid & 3) * 32;

    float acc[4][4][4];
    #pragma unroll
    for (int a = 0; a < 4; a++)
        #pragma unroll
        for (int b = 0; b < 4; b++)
            #pragma unroll
            for (int c = 0; c < 4; c++) acc[a][b][c] = 0.f;

    auto loadStage = [&](int c) {
        const int kt = kbase + (c << 6);
        const uint32_t base = sb + (c % NSTAGE) * STAGE_SZ;
        #pragma unroll
        for (int it = 0; it < 4; it++) {
            int lin = it * 256 + tid;
            int row = lin >> 3, ch = lin & 7;
            uint32_t d = base + row * 128 + (((ch ^ (row & 7)) << 4));
            size_t aoff = (size_t)(bRow + row) * lda + kt + ch * 8;
            cp16(d, A + aoff, 16);
            int bn = bCol + row;
            int ok = (bn < N) ? 16 : 0;
            size_t boff = (size_t)(bn < N ? bn : 0) * ldb + kt + ch * 8;
            cp16(d + 16384, B + boff, ok);
        }
        CP_COMMIT();
    };

    loadStage(0);
    if (nChunks > 1) loadStage(1);
    for (int c = 0; c < nChunks; c++) {
        if (c + 1 < nChunks) { CP_WAIT(1); }
        else                 { CP_WAIT(0); }
        __syncthreads();
        // Safe post-barrier: stage (c+2)%3 was last read in chunk c-1, and
        // every warp finished chunk c-1 before passing this barrier.
        if (c + 2 < nChunks) loadStage(c + 2);

        const uint32_t st = sb + (c % NSTAGE) * STAGE_SZ;
        const int hkA = l >> 4;
        const int matb = l >> 3;
        const int rB0 = wn + (l & 7) + ((matb >> 1) << 3);
        const int hkB = matb & 1;

        #pragma unroll
        for (int ks = 0; ks < 4; ks++) {
            uint32_t Af[4][4], Bf[4][2];
            #pragma unroll
            for (int mi = 0; mi < 4; mi++) {
                int r = wm + mi * 16 + (l & 15);
                int ck = 2 * ks + hkA;
                uint32_t ad = st + r * 128 + ((ck ^ (r & 7)) << 4);
                ldm_x4(Af[mi][0], Af[mi][1], Af[mi][2], Af[mi][3], ad);
            }
            #pragma unroll
            for (int ng = 0; ng < 2; ng++) {
                int r = rB0 + ng * 16;
                int ck = 2 * ks + hkB;
                uint32_t ad = st + 16384 + r * 128 + ((ck ^ (r & 7)) << 4);
                uint32_t t0, t1, t2, t3;
                ldm_x4(t0, t1, t2, t3, ad);
                Bf[ng*2][0] = t0; Bf[ng*2][1] = t1;
                Bf[ng*2+1][0] = t2; Bf[ng*2+1][1] = t3;
            }
            #pragma unroll
            for (int mi = 0; mi < 4; mi++)
                #pragma unroll
                for (int ni = 0; ni < 4; ni++)
                    mma16816(acc[mi][ni], Af[mi], Bf[ni]);
        }
    }

    if (TRANS) {
        __syncthreads();   // stage smem about to be reused
        float* ts = reinterpret_cast<float*>(smem);   // [128][132]
        #pragma unroll
        for (int mi = 0; mi < 4; mi++) {
            #pragma unroll
            for (int h2 = 0; h2 < 2; h2++) {
                int row = wm + mi * 16 + h2 * 8 + (l >> 2);
                #pragma unroll
                for (int ni = 0; ni < 4; ni++) {
                    int col = wn + ni * 8 + (l & 3) * 2;
                    float v0 = acc[mi][ni][h2 * 2 + 0];
                    float v1 = acc[mi][ni][h2 * 2 + 1];
                    if (EPI == 1) {
                        v0 = softplus_f(v0 + bias[bCol + col]);
                        v1 = softplus_f(v1 + bias[bCol + col + 1]);
                    }
                    ts[(col) * 132 + row] = v0;
                    ts[(col + 1) * 132 + row] = v1;
                }
            }
        }
        __syncthreads();
        f16* Ch = reinterpret_cast<f16*>(Cv);
        #pragma unroll
        for (int i = 0; i < 32; i++) {
            int idx = i * 256 + tid;
            int r = idx >> 6, c2 = (idx & 63) * 2;
            uint v = pack2(__float2half_rn(ts[r * 132 + c2]),
                           __float2half_rn(ts[r * 132 + c2 + 1]));
            *reinterpret_cast<uint*>(Ch + (size_t)(bCol + r) * ldc + bRow + c2) = v;
        }
    } else {
        #pragma unroll
        for (int mi = 0; mi < 4; mi++) {
            #pragma unroll
            for (int h2 = 0; h2 < 2; h2++) {
                int row = bRow + wm + mi * 16 + h2 * 8 + (l >> 2);
                #pragma unroll
                for (int ni = 0; ni < 4; ni++) {
                    int col = bCol + wn + ni * 8 + (l & 3) * 2;
                    if (col < N) {
                        float v0 = acc[mi][ni][h2 * 2 + 0];
                        float v1 = acc[mi][ni][h2 * 2 + 1];
                        if (EPI == 1) {
                            v0 = softplus_f(v0 + bias[col]);
                            v1 = softplus_f(v1 + bias[col + 1]);
                        } else if (EPI == 2) {
                            const float* rr = res + (size_t)row * ldres + col;
                            v0 += rr[0]; v1 += rr[1];
                        }
                        if (HOUT) {
                            f16* Ch = reinterpret_cast<f16*>(Cv);
                            *reinterpret_cast<uint*>(
                                Ch + (size_t)row * ldc + col) =
                                pack2(__float2half_rn(v0), __float2half_rn(v1));
                        } else {
                            float* Cf = reinterpret_cast<float*>(Cv) +
                                        (long)blockIdx.z * partStride;
                            *reinterpret_cast<float2*>(
                                Cf + (size_t)row * ldc + col) =
                                make_float2(v0, v1);
                        }
                    }
                }
            }
        }
    }
}

// ---------------------------------------------------------------------------
// all weights fp32 -> fp16 in one launch
// ---------------------------------------------------------------------------
#define NW0 (2 * DINNER * DMODEL / 4)
#define NW1 (XPROJ_N * DINNER / 4)
#define NW2 (DINNER * DTRANK / 4)
#define NW3 (DMODEL * DINNER / 4)
#define NWTOT (NW0 + NW1 + NW2 + NW3)

__global__ __launch_bounds__(256) void convert_all(
    const float* __restrict__ w0, f16* __restrict__ o0,
    const float* __restrict__ w1, f16* __restrict__ o1,
    const float* __restrict__ w2, f16* __restrict__ o2,
    const float* __restrict__ w3, f16* __restrict__ o3)
{
    int i = blockIdx.x * 256 + threadIdx.x;
    const float* w; f16* o; int j;
    if (i < NW0)                  { w = w0; o = o0; j = i; }
    else if (i < NW0 + NW1)       { w = w1; o = o1; j = i - NW0; }
    else if (i < NW0 + NW1 + NW2) { w = w2; o = o2; j = i - NW0 - NW1; }
    else if (i < NWTOT)           { w = w3; o = o3; j = i - NW0 - NW1 - NW2; }
    else return;
    float4 v = reinterpret_cast<const float4*>(w)[j];
    reinterpret_cast<uint2*>(o)[j] = cvt4(v);
}

// ---------------------------------------------------------------------------
// RMSNorm -> fp16
// ---------------------------------------------------------------------------
__global__ __launch_bounds__(256) void rmsnorm_kernel(
    const float* __restrict__ x, const float* __restrict__ w,
    f16* __restrict__ hh)
{
    int row = blockIdx.x;
    int tid = threadIdx.x;
    float4 v = reinterpret_cast<const float4*>(x + (size_t)row * DMODEL)[tid];
    float ss = v.x * v.x + v.y * v.y + v.z * v.z + v.w * v.w;
    __shared__ float red[8];
    #pragma unroll
    for (int o = 16; o > 0; o >>= 1) ss += __shfl_xor_sync(0xffffffffu, ss, o);
    if ((tid & 31) == 0) red[tid >> 5] = ss;
    __syncthreads();
    if (tid < 32) {
        float t = (tid < 8) ? red[tid] : 0.f;
        #pragma unroll
        for (int o = 4; o > 0; o >>= 1) t += __shfl_xor_sync(0xffffffffu, t, o);
        if (tid == 0) red[0] = t;
    }
    __syncthreads();
    float scale = rsqrtf(red[0] * (1.0f / DMODEL) + 1e-5f);
    float4 wv = reinterpret_cast<const float4*>(w)[tid];
    float4 o;
    o.x = v.x * scale * wv.x;  o.y = v.y * scale * wv.y;
    o.z = v.z * scale * wv.z;  o.w = v.w * scale * wv.w;
    reinterpret_cast<uint2*>(hh + (size_t)row * DMODEL)[tid] = cvt4(o);
}

// ---------------------------------------------------------------------------
// Tiled conv(width4)+SiLU + silu(z), half2-vectorized, packed smem.
// ---------------------------------------------------------------------------
#define CT 32
#define CD 64

__global__ __launch_bounds__(256) void conv_silu_kernel(
    const f16* __restrict__ xz,
    const float* __restrict__ conv_w, const float* __restrict__ conv_b,
    f16* __restrict__ xsh, f16* __restrict__ xsT, f16* __restrict__ gT)
{
    __shared__ uint xc2[CT + 3][CD / 2];
    __shared__ uint sxu[CD / 2][CT + 1];
    __shared__ uint sgu[CD / 2][CT + 1];

    const int tid = threadIdx.x;
    const int d0 = blockIdx.x * CD;
    const int t0 = blockIdx.y * CT;
    const bool halo = (t0 & (SEQ - 1)) != 0;

    #pragma unroll
    for (int it = 0; it < 5; it++) {
        int lin = it * 256 + tid;
        if (lin < (CT + 3) * (CD / 2)) {
            int i = lin >> 5, c2 = lin & 31;
            uint v = 0;
            if (i >= 3 || halo)
                v = *reinterpret_cast<const uint*>(
                    xz + (size_t)(t0 - 3 + i) * (2 * DINNER) + d0 + c2 * 2);
            xc2[i][c2] = v;
        }
    }
    __syncthreads();

    #pragma unroll
    for (int it = 0; it < 4; it++) {
        int lin = it * 256 + tid;
        int tok = lin >> 5, c2 = lin & 31;
        int d = d0 + c2 * 2;
        float2 a = *reinterpret_cast<const float2*>(conv_b + d);
        #pragma unroll
        for (int k = 0; k < DCONV; k++) {
            uint xu = xc2[tok + k][c2];
            float2 xf = __half22float2(*reinterpret_cast<__half2*>(&xu));
            a.x = fmaf(conv_w[d * DCONV + k],       xf.x, a.x);
            a.y = fmaf(conv_w[(d + 1) * DCONV + k], xf.y, a.y);
        }
        uint zu = *reinterpret_cast<const uint*>(
            xz + (size_t)(t0 + tok) * (2 * DINNER) + DINNER + d);
        float2 zf = __half22float2(*reinterpret_cast<__half2*>(&zu));
        uint xsp = pack2(__float2half_rn(silu_f(a.x)),
                         __float2half_rn(silu_f(a.y)));
        *reinterpret_cast<uint*>(xsh + (size_t)(t0 + tok) * DINNER + d) = xsp;
        sxu[c2][tok] = xsp;
        sgu[c2][tok] = pack2(__float2half_rn(silu_f(zf.x)),
                             __float2half_rn(silu_f(zf.y)));
    }
    __syncthreads();

    #pragma unroll
    for (int it = 0; it < 4; it++) {
        int lin = it * 256 + tid;
        int ch = lin >> 4, tp = (lin & 15) * 2;
        int r = ch >> 1;
        uint sel = (ch & 1) ? 0x7632u : 0x5410u;
        uint xa = sxu[r][tp], xb = sxu[r][tp + 1];
        uint ga = sgu[r][tp], gb = sgu[r][tp + 1];
        size_t o = (size_t)(d0 + ch) * NTOK + t0 + tp;
        *reinterpret_cast<uint*>(xsT + o) = __byte_perm(xa, xb, sel);
        *reinterpret_cast<uint*>(gT + o)  = __byte_perm(ga, gb, sel);
    }
}

// ---------------------------------------------------------------------------
// split-K reduce for x_proj
// ---------------------------------------------------------------------------
__global__ __launch_bounds__(256) void reduce_xproj(
    const float* __restrict__ part,
    f16* __restrict__ xdh,
    float* __restrict__ bcT)
{
    int idx = blockIdx.x * 256 + threadIdx.x;
    if (idx >= NTOK * XPROJ_N) return;
    float s = 0.f;
    #pragma unroll
    for (int z = 0; z < XSPLIT; z++) s += part[(size_t)z * NTOK * XPROJ_N + idx];
    xdh[idx] = __float2half_rn(s);
    int row = idx / XPROJ_N, col = idx - row * XPROJ_N;
    if (col >= DTRANK)
        bcT[(size_t)(col - DTRANK) * NTOK + row] = s;
}

// ---------------------------------------------------------------------------
// selective scan + gate
// ---------------------------------------------------------------------------
__global__ __launch_bounds__(256) void scan_kernel(
    const f16* __restrict__ dtT, const f16* __restrict__ xsT,
    const float* __restrict__ bcT, const f16* __restrict__ gT,
    const float* __restrict__ A_log, const float* __restrict__ Dp,
    f16* __restrict__ yT)
{
    int warp = threadIdx.x >> 5;
    int lane = threadIdx.x & 31;
    int chPair = blockIdx.x * 8 + warp;
    int ch = chPair * 2 + (lane >> 4);
    int b = ch >> 11;
    int d = ch & 2047;
    int n = lane & 15;
    int rowBase = b * SEQ;

    const f16* dtp = dtT + (size_t)d * NTOK + rowBase;
    const f16* xsp = xsT + (size_t)d * NTOK + rowBase;
    const f16* gp  = gT  + (size_t)d * NTOK + rowBase;
    const float* Bp = bcT + (size_t)n * NTOK + rowBase;
    const float* Cp = bcT + (size_t)(DSTATE + n) * NTOK + rowBase;
    f16* yp = yT + (size_t)d * NTOK + rowBase;

    float a  = -expf(A_log[d * DSTATE + n]);
    float Dv = Dp[d];
    float s = 0.f;

    uint2 dtu = *reinterpret_cast<const uint2*>(dtp);
    uint2 xsu = *reinterpret_cast<const uint2*>(xsp);
    uint2 gu  = *reinterpret_cast<const uint2*>(gp);
    float4 B4 = *reinterpret_cast<const float4*>(Bp);
    float4 C4 = *reinterpret_cast<const float4*>(Cp);

    for (int t = 0; t < SEQ; t += 4) {
        uint2 ndt, nxs, ng; float4 nB, nC;
        if (t + 4 < SEQ) {
            ndt = *reinterpret_cast<const uint2*>(dtp + t + 4);
            nxs = *reinterpret_cast<const uint2*>(xsp + t + 4);
            ng  = *reinterpret_cast<const uint2*>(gp + t + 4);
            nB  = *reinterpret_cast<const float4*>(Bp + t + 4);
            nC  = *reinterpret_cast<const float4*>(Cp + t + 4);
        }
        float dtv[4], xsv[4], gv[4];
        unpack4(dtu, dtv); unpack4(xsu, xsv); unpack4(gu, gv);
        const float* Bv = &B4.x; const float* Cv = &C4.x;
        float yv[4];
        #pragma unroll
        for (int q = 0; q < 4; q++) {
            float dA = __expf(dtv[q] * a);
            s = fmaf(dA, s, dtv[q] * xsv[q] * Bv[q]);
            float p = s * Cv[q];
            p += __shfl_xor_sync(0xffffffffu, p, 8);
            p += __shfl_xor_sync(0xffffffffu, p, 4);
            p += __shfl_xor_sync(0xffffffffu, p, 2);
            p += __shfl_xor_sync(0xffffffffu, p, 1);
            yv[q] = (p + Dv * xsv[q]) * gv[q];
        }
        if (n == 0) {
            uint2 yo;
            yo.x = pack2(__float2half_rn(yv[0]), __float2half_rn(yv[1]));
            yo.y = pack2(__float2half_rn(yv[2]), __float2half_rn(yv[3]));
            *reinterpret_cast<uint2*>(yp + t) = yo;
        }
        dtu = ndt; xsu = nxs; gu = ng; B4 = nB; C4 = nC;
    }
}

// ---------------------------------------------------------------------------
// yT fp16 [DINNER][NTOK] -> y fp16 [NTOK][DINNER]
// ---------------------------------------------------------------------------
__global__ __launch_bounds__(256) void transpose_y(
    const f16* __restrict__ yT, f16* __restrict__ yh)
{
    __shared__ f16 tile[64][34];
    int bx = blockIdx.x, by = blockIdx.y;
    #pragma unroll
    for (int it = 0; it < 4; it++) {
        int lin = it * 256 + threadIdx.x;
        int dd = lin >> 4, t2 = (lin & 15) * 2;
        uint v = *reinterpret_cast<const uint*>(
            yT + (size_t)(by * 64 + dd) * NTOK + bx * 32 + t2);
        __half2 h = *reinterpret_cast<__half2*>(&v);
        tile[dd][t2] = __low2half(h);
        tile[dd][t2 + 1] = __high2half(h);
    }
    __syncthreads();
    #pragma unroll
    for (int it = 0; it < 4; it++) {
        int lin = it * 256 + threadIdx.x;
        int tok = lin >> 5, d2 = (lin & 31) * 2;
        uint v = pack2(tile[d2][tok], tile[d2 + 1][tok]);
        *reinterpret_cast<uint*>(
            yh + (size_t)(bx * 32 + tok) * DINNER + by * 64 + d2) = v;
    }
}

// ---------------------------------------------------------------------------
// Launch
// ---------------------------------------------------------------------------
extern "C" void kernel_launch(void* const* d_in, const int* in_sizes, int n_in,
                              void* d_out, int out_size)
{
    const float* x         = (const float*)d_in[0];
    const float* norm_w    = (const float*)d_in[1];
    const float* in_proj_w = (const float*)d_in[2];
    const float* conv_w    = (const float*)d_in[3];
    const float* conv_b    = (const float*)d_in[4];
    const float* x_proj_w  = (const float*)d_in[5];
    const float* dt_proj_w = (const float*)d_in[6];
    const float* dt_proj_b = (const float*)d_in[7];
    const float* A_log     = (const float*)d_in[8];
    const float* Dp        = (const float*)d_in[9];
    const float* out_proj_w= (const float*)d_in[10];
    float* out = (float*)d_out;

    float *pbcT, *ppart;
    f16 *pwi, *pwx, *pwd, *pwo, *phh, *pxz, *pxsh, *pxsT, *pgT, *pdtT, *pyT,
        *pxdh, *pyh;
    cudaGetSymbolAddress((void**)&pbcT, g_bcT);
    cudaGetSymbolAddress((void**)&ppart,g_part);
    cudaGetSymbolAddress((void**)&pwi,  g_wi);
    cudaGetSymbolAddress((void**)&pwx,  g_wx);
    cudaGetSymbolAddress((void**)&pwd,  g_wd);
    cudaGetSymbolAddress((void**)&pwo,  g_wo);
    cudaGetSymbolAddress((void**)&phh,  g_hh);
    cudaGetSymbolAddress((void**)&pxz,  g_xz);
    cudaGetSymbolAddress((void**)&pxsh, g_xsh);
    cudaGetSymbolAddress((void**)&pxsT, g_xsT);
    cudaGetSymbolAddress((void**)&pgT,  g_gT);
    cudaGetSymbolAddress((void**)&pdtT, g_dtT);
    cudaGetSymbolAddress((void**)&pyT,  g_yT);
    cudaGetSymbolAddress((void**)&pxdh, g_xdh);
    cudaGetSymbolAddress((void**)&pyh,  g_yh);

    cudaFuncSetAttribute(mma_gemm<0,0,0>, cudaFuncAttributeMaxDynamicSharedMemorySize, GEMM_SMEM);
    cudaFuncSetAttribute(mma_gemm<0,0,1>, cudaFuncAttributeMaxDynamicSharedMemorySize, GEMM_SMEM);
    cudaFuncSetAttribute(mma_gemm<1,1,1>, cudaFuncAttributeMaxDynamicSharedMemorySize, GEMM_SMEM);
    cudaFuncSetAttribute(mma_gemm<2,0,0>, cudaFuncAttributeMaxDynamicSharedMemorySize, GEMM_SMEM);

    // 0) all weight conversions in one launch
    convert_all<<<(NWTOT + 255) / 256, 256>>>(
        in_proj_w, pwi, x_proj_w, pwx, dt_proj_w, pwd, out_proj_w, pwo);

    // 1) RMSNorm
    rmsnorm_kernel<<<NTOK, 256>>>(x, norm_w, phh);

    // 2) in_proj -> xz fp16
    {
        dim3 grid((2 * DINNER) / 128, NTOK / 128, 1);
        mma_gemm<0,0,1><<<grid, 256, GEMM_SMEM>>>(
            phh, DMODEL, pwi, DMODEL,
            pxz, 2 * DINNER, 2 * DINNER, DMODEL, 0, nullptr, nullptr, 0);
    }

    // 3) conv + silu
    {
        dim3 grid(DINNER / CD, NTOK / CT);
        conv_silu_kernel<<<grid, 256>>>(pxz, conv_w, conv_b,
                                        pxsh, pxsT, pgT);
    }

    // 4) x_proj split-K -> fp32 partials
    {
        dim3 grid(1, NTOK / 128, XSPLIT);
        mma_gemm<0,0,0><<<grid, 256, GEMM_SMEM>>>(
            pxsh, DINNER, pwx, DINNER,
            ppart, XPROJ_N, XPROJ_N, DINNER / XSPLIT,
            (long)NTOK * XPROJ_N, nullptr, nullptr, 0);
    }
    reduce_xproj<<<(NTOK * XPROJ_N + 255) / 256, 256>>>(ppart, pxdh, pbcT);

    // 5) dt_proj + softplus -> dtT fp16
    {
        dim3 grid(DINNER / 128, NTOK / 128, 1);
        mma_gemm<1,1,1><<<grid, 256, GEMM_SMEM>>>(
            pxdh, XPROJ_N, pwd, DTRANK,
            pdtT, NTOK, DINNER, DTRANK, 0, dt_proj_b, nullptr, 0);
    }

    // 6) scan -> yT fp16
    scan_kernel<<<(BATCH * DINNER) / 16, 256>>>(pdtT, pxsT, pbcT, pgT,
                                                A_log, Dp, pyT);

    // 7) transpose y
    {
        dim3 grid(NTOK / 32, DINNER / 64);
        transpose_y<<<grid, 256>>>(pyT, pyh);
    }

    // 8) out_proj + residual (direct, fused epilogue)
    {
        dim3 grid(DMODEL / 128, NTOK / 128, 1);
        mma_gemm<2,0,0><<<grid, 256, GEMM_SMEM>>>(
            pyh, DINNER, pwo, DINNER,
            out, DMODEL, DMODEL, DINNER, 0, nullptr, x, DMODEL);
    }
}

// round 15
// speedup vs baseline: 1.0703x; 1.0146x over previous
#include <cuda_runtime.h>
#include <cuda_fp16.h>
#include <cstdint>
#include <math.h>

// ---------------------------------------------------------------------------
// Mamba block forward. GEMMs via mma.sync HMMA fp16 single-pass (fp32 accum).
// 128x128 CTA tiles, 8 warps (64x32), 3-stage cp.async, 2 CTAs/SM.
// Scan writes token-major y directly (fused transpose via smem staging).
// ---------------------------------------------------------------------------

#define BATCH   2
#define SEQ     1024
#define DMODEL  1024
#define DINNER  2048
#define DSTATE  16
#define DTRANK  64
#define DCONV   4
#define NTOK    (BATCH * SEQ)
#define XPROJ_N (DTRANK + 2 * DSTATE)   // 96
#define XSPLIT  16

typedef __half f16;

// fp32 scratch
__device__ __align__(256) float g_bcT[2 * DSTATE * NTOK];
__device__ __align__(256) float g_part[XSPLIT * NTOK * XPROJ_N];

// fp16 weights + activations
__device__ __align__(256) f16 g_wi[2 * DINNER * DMODEL];
__device__ __align__(256) f16 g_wx[XPROJ_N * DINNER];
__device__ __align__(256) f16 g_wd[DINNER * DTRANK];
__device__ __align__(256) f16 g_wo[DMODEL * DINNER];
__device__ __align__(256) f16 g_hh[NTOK * DMODEL];
__device__ __align__(256) f16 g_xz[NTOK * 2 * DINNER];
__device__ __align__(256) f16 g_xsh[NTOK * DINNER];
__device__ __align__(256) f16 g_xsT[DINNER * NTOK];
__device__ __align__(256) f16 g_gT[DINNER * NTOK];
__device__ __align__(256) f16 g_dtT[DINNER * NTOK];
__device__ __align__(256) f16 g_xdh[NTOK * XPROJ_N];
__device__ __align__(256) f16 g_yh[NTOK * DINNER];

// ---------------------------------------------------------------------------
// helpers
// ---------------------------------------------------------------------------
__device__ __forceinline__ uint32_t smem_u32(const void* p) {
    uint32_t a;
    asm("{ .reg .u64 t; cvta.to.shared.u64 t, %1; cvt.u32.u64 %0, t; }"
        : "=r"(a) : "l"(p));
    return a;
}
__device__ __forceinline__ void ldm_x4(uint32_t& r0, uint32_t& r1,
                                       uint32_t& r2, uint32_t& r3, uint32_t a) {
    asm volatile("ldmatrix.sync.aligned.m8n8.x4.shared.b16 {%0,%1,%2,%3}, [%4];"
                 : "=r"(r0), "=r"(r1), "=r"(r2), "=r"(r3) : "r"(a));
}
__device__ __forceinline__ void mma16816(float* d, const uint32_t* a,
                                         const uint32_t* b) {
    asm volatile(
        "mma.sync.aligned.m16n8k16.row.col.f32.f16.f16.f32 "
        "{%0,%1,%2,%3}, {%4,%5,%6,%7}, {%8,%9}, {%0,%1,%2,%3};"
        : "+f"(d[0]), "+f"(d[1]), "+f"(d[2]), "+f"(d[3])
        : "r"(a[0]), "r"(a[1]), "r"(a[2]), "r"(a[3]), "r"(b[0]), "r"(b[1]));
}
__device__ __forceinline__ void cp16(uint32_t dst, const void* src, int sz) {
    asm volatile("cp.async.cg.shared.global [%0], [%1], 16, %2;"
                 :: "r"(dst), "l"(src), "r"(sz) : "memory");
}
#define CP_COMMIT() asm volatile("cp.async.commit_group;" ::: "memory")
#define CP_WAIT(n)  asm volatile("cp.async.wait_group %0;" :: "n"(n) : "memory")

__device__ __forceinline__ uint32_t pack2(f16 a, f16 b) {
    return ((uint32_t)__half_as_ushort(b) << 16) | __half_as_ushort(a);
}
__device__ __forceinline__ uint2 cvt4(float4 v) {
    uint2 r;
    r.x = pack2(__float2half_rn(v.x), __float2half_rn(v.y));
    r.y = pack2(__float2half_rn(v.z), __float2half_rn(v.w));
    return r;
}
__device__ __forceinline__ void unpack4(uint2 u, float* f) {
    __half2 a = *reinterpret_cast<__half2*>(&u.x);
    __half2 b = *reinterpret_cast<__half2*>(&u.y);
    float2 fa = __half22float2(a), fb = __half22float2(b);
    f[0] = fa.x; f[1] = fa.y; f[2] = fb.x; f[3] = fb.y;
}
__device__ __forceinline__ float softplus_f(float v) {
    return (v > 15.f) ? v : log1pf(__expf(v));
}
__device__ __forceinline__ float silu_f(float v) {
    return v / (1.f + __expf(-v));
}

// ---------------------------------------------------------------------------
// HMMA GEMM (NT): C[M,N] = A[M,K]·B[N,K]^T, fp16 x fp16 -> fp32 accum.
// CTA 128x128, 8 warps (64x32), K-chunk 64, 3-stage cp.async, 2 CTAs/SM.
// One __syncthreads per chunk (loadStage issued post-barrier).
// EPI: 0 none, 1 softplus(acc+bias[n]), 2 acc+res[m,n] (fp32 out).
// TRANS: transposed fp16 store.  HOUT: 1 fp16 out, else fp32 (+split-K).
// ---------------------------------------------------------------------------
#define STAGE_SZ 32768
#define NSTAGE 3
#define GEMM_SMEM (NSTAGE * STAGE_SZ)   // 96 KB

template<int EPI, int TRANS, int HOUT>
__global__ void __launch_bounds__(256, 2) mma_gemm(
    const f16* __restrict__ A, int lda,
    const f16* __restrict__ B, int ldb,
    void* __restrict__ Cv, int ldc, int N, int Ksplit, long partStride,
    const float* __restrict__ bias,
    const float* __restrict__ res, int ldres)
{
    extern __shared__ char smem[];
    const uint32_t sb = smem_u32(smem);
    const int tid = threadIdx.x;
    const int bRow = blockIdx.y * 128, bCol = blockIdx.x * 128;
    const int kbase = blockIdx.z * Ksplit;
    const int nChunks = Ksplit >> 6;

    const int wid = tid >> 5, l = tid & 31;
    const int wm = (wid >> 2) * 64, wn = (wid & 3) * 32;

    float acc[4][4][4];
    #pragma unroll
    for (int a = 0; a < 4; a++)
        #pragma unroll
        for (int b = 0; b < 4; b++)
            #pragma unroll
            for (int c = 0; c < 4; c++) acc[a][b][c] = 0.f;

    auto loadStage = [&](int c) {
        const int kt = kbase + (c << 6);
        const uint32_t base = sb + (c % NSTAGE) * STAGE_SZ;
        #pragma unroll
        for (int it = 0; it < 4; it++) {
            int lin = it * 256 + tid;
            int row = lin >> 3, ch = lin & 7;
            uint32_t d = base + row * 128 + (((ch ^ (row & 7)) << 4));
            size_t aoff = (size_t)(bRow + row) * lda + kt + ch * 8;
            cp16(d, A + aoff, 16);
            int bn = bCol + row;
            int ok = (bn < N) ? 16 : 0;
            size_t boff = (size_t)(bn < N ? bn : 0) * ldb + kt + ch * 8;
            cp16(d + 16384, B + boff, ok);
        }
        CP_COMMIT();
    };

    loadStage(0);
    if (nChunks > 1) loadStage(1);
    for (int c = 0; c < nChunks; c++) {
        if (c + 1 < nChunks) { CP_WAIT(1); }
        else                 { CP_WAIT(0); }
        __syncthreads();
        if (c + 2 < nChunks) loadStage(c + 2);

        const uint32_t st = sb + (c % NSTAGE) * STAGE_SZ;
        const int hkA = l >> 4;
        const int matb = l >> 3;
        const int rB0 = wn + (l & 7) + ((matb >> 1) << 3);
        const int hkB = matb & 1;

        #pragma unroll
        for (int ks = 0; ks < 4; ks++) {
            uint32_t Af[4][4], Bf[4][2];
            #pragma unroll
            for (int mi = 0; mi < 4; mi++) {
                int r = wm + mi * 16 + (l & 15);
                int ck = 2 * ks + hkA;
                uint32_t ad = st + r * 128 + ((ck ^ (r & 7)) << 4);
                ldm_x4(Af[mi][0], Af[mi][1], Af[mi][2], Af[mi][3], ad);
            }
            #pragma unroll
            for (int ng = 0; ng < 2; ng++) {
                int r = rB0 + ng * 16;
                int ck = 2 * ks + hkB;
                uint32_t ad = st + 16384 + r * 128 + ((ck ^ (r & 7)) << 4);
                uint32_t t0, t1, t2, t3;
                ldm_x4(t0, t1, t2, t3, ad);
                Bf[ng*2][0] = t0; Bf[ng*2][1] = t1;
                Bf[ng*2+1][0] = t2; Bf[ng*2+1][1] = t3;
            }
            #pragma unroll
            for (int mi = 0; mi < 4; mi++)
                #pragma unroll
                for (int ni = 0; ni < 4; ni++)
                    mma16816(acc[mi][ni], Af[mi], Bf[ni]);
        }
    }

    if (TRANS) {
        __syncthreads();
        float* ts = reinterpret_cast<float*>(smem);   // [128][132]
        #pragma unroll
        for (int mi = 0; mi < 4; mi++) {
            #pragma unroll
            for (int h2 = 0; h2 < 2; h2++) {
                int row = wm + mi * 16 + h2 * 8 + (l >> 2);
                #pragma unroll
                for (int ni = 0; ni < 4; ni++) {
                    int col = wn + ni * 8 + (l & 3) * 2;
                    float v0 = acc[mi][ni][h2 * 2 + 0];
                    float v1 = acc[mi][ni][h2 * 2 + 1];
                    if (EPI == 1) {
                        v0 = softplus_f(v0 + bias[bCol + col]);
                        v1 = softplus_f(v1 + bias[bCol + col + 1]);
                    }
                    ts[(col) * 132 + row] = v0;
                    ts[(col + 1) * 132 + row] = v1;
                }
            }
        }
        __syncthreads();
        f16* Ch = reinterpret_cast<f16*>(Cv);
        #pragma unroll
        for (int i = 0; i < 32; i++) {
            int idx = i * 256 + tid;
            int r = idx >> 6, c2 = (idx & 63) * 2;
            uint v = pack2(__float2half_rn(ts[r * 132 + c2]),
                           __float2half_rn(ts[r * 132 + c2 + 1]));
            *reinterpret_cast<uint*>(Ch + (size_t)(bCol + r) * ldc + bRow + c2) = v;
        }
    } else {
        #pragma unroll
        for (int mi = 0; mi < 4; mi++) {
            #pragma unroll
            for (int h2 = 0; h2 < 2; h2++) {
                int row = bRow + wm + mi * 16 + h2 * 8 + (l >> 2);
                #pragma unroll
                for (int ni = 0; ni < 4; ni++) {
                    int col = bCol + wn + ni * 8 + (l & 3) * 2;
                    if (col < N) {
                        float v0 = acc[mi][ni][h2 * 2 + 0];
                        float v1 = acc[mi][ni][h2 * 2 + 1];
                        if (EPI == 1) {
                            v0 = softplus_f(v0 + bias[col]);
                            v1 = softplus_f(v1 + bias[col + 1]);
                        } else if (EPI == 2) {
                            const float* rr = res + (size_t)row * ldres + col;
                            v0 += rr[0]; v1 += rr[1];
                        }
                        if (HOUT) {
                            f16* Ch = reinterpret_cast<f16*>(Cv);
                            *reinterpret_cast<uint*>(
                                Ch + (size_t)row * ldc + col) =
                                pack2(__float2half_rn(v0), __float2half_rn(v1));
                        } else {
                            float* Cf = reinterpret_cast<float*>(Cv) +
                                        (long)blockIdx.z * partStride;
                            *reinterpret_cast<float2*>(
                                Cf + (size_t)row * ldc + col) =
                                make_float2(v0, v1);
                        }
                    }
                }
            }
        }
    }
}

// ---------------------------------------------------------------------------
// all weights fp32 -> fp16 in one launch
// ---------------------------------------------------------------------------
#define NW0 (2 * DINNER * DMODEL / 4)
#define NW1 (XPROJ_N * DINNER / 4)
#define NW2 (DINNER * DTRANK / 4)
#define NW3 (DMODEL * DINNER / 4)
#define NWTOT (NW0 + NW1 + NW2 + NW3)

__global__ __launch_bounds__(256) void convert_all(
    const float* __restrict__ w0, f16* __restrict__ o0,
    const float* __restrict__ w1, f16* __restrict__ o1,
    const float* __restrict__ w2, f16* __restrict__ o2,
    const float* __restrict__ w3, f16* __restrict__ o3)
{
    int i = blockIdx.x * 256 + threadIdx.x;
    const float* w; f16* o; int j;
    if (i < NW0)                  { w = w0; o = o0; j = i; }
    else if (i < NW0 + NW1)       { w = w1; o = o1; j = i - NW0; }
    else if (i < NW0 + NW1 + NW2) { w = w2; o = o2; j = i - NW0 - NW1; }
    else if (i < NWTOT)           { w = w3; o = o3; j = i - NW0 - NW1 - NW2; }
    else return;
    float4 v = reinterpret_cast<const float4*>(w)[j];
    reinterpret_cast<uint2*>(o)[j] = cvt4(v);
}

// ---------------------------------------------------------------------------
// RMSNorm -> fp16
// ---------------------------------------------------------------------------
__global__ __launch_bounds__(256) void rmsnorm_kernel(
    const float* __restrict__ x, const float* __restrict__ w,
    f16* __restrict__ hh)
{
    int row = blockIdx.x;
    int tid = threadIdx.x;
    float4 v = reinterpret_cast<const float4*>(x + (size_t)row * DMODEL)[tid];
    float ss = v.x * v.x + v.y * v.y + v.z * v.z + v.w * v.w;
    __shared__ float red[8];
    #pragma unroll
    for (int o = 16; o > 0; o >>= 1) ss += __shfl_xor_sync(0xffffffffu, ss, o);
    if ((tid & 31) == 0) red[tid >> 5] = ss;
    __syncthreads();
    if (tid < 32) {
        float t = (tid < 8) ? red[tid] : 0.f;
        #pragma unroll
        for (int o = 4; o > 0; o >>= 1) t += __shfl_xor_sync(0xffffffffu, t, o);
        if (tid == 0) red[0] = t;
    }
    __syncthreads();
    float scale = rsqrtf(red[0] * (1.0f / DMODEL) + 1e-5f);
    float4 wv = reinterpret_cast<const float4*>(w)[tid];
    float4 o;
    o.x = v.x * scale * wv.x;  o.y = v.y * scale * wv.y;
    o.z = v.z * scale * wv.z;  o.w = v.w * scale * wv.w;
    reinterpret_cast<uint2*>(hh + (size_t)row * DMODEL)[tid] = cvt4(o);
}

// ---------------------------------------------------------------------------
// Tiled conv(width4)+SiLU + silu(z), half2-vectorized, packed smem.
// ---------------------------------------------------------------------------
#define CT 32
#define CD 64

__global__ __launch_bounds__(256) void conv_silu_kernel(
    const f16* __restrict__ xz,
    const float* __restrict__ conv_w, const float* __restrict__ conv_b,
    f16* __restrict__ xsh, f16* __restrict__ xsT, f16* __restrict__ gT)
{
    __shared__ uint xc2[CT + 3][CD / 2];
    __shared__ uint sxu[CD / 2][CT + 1];
    __shared__ uint sgu[CD / 2][CT + 1];

    const int tid = threadIdx.x;
    const int d0 = blockIdx.x * CD;
    const int t0 = blockIdx.y * CT;
    const bool halo = (t0 & (SEQ - 1)) != 0;

    #pragma unroll
    for (int it = 0; it < 5; it++) {
        int lin = it * 256 + tid;
        if (lin < (CT + 3) * (CD / 2)) {
            int i = lin >> 5, c2 = lin & 31;
            uint v = 0;
            if (i >= 3 || halo)
                v = *reinterpret_cast<const uint*>(
                    xz + (size_t)(t0 - 3 + i) * (2 * DINNER) + d0 + c2 * 2);
            xc2[i][c2] = v;
        }
    }
    __syncthreads();

    #pragma unroll
    for (int it = 0; it < 4; it++) {
        int lin = it * 256 + tid;
        int tok = lin >> 5, c2 = lin & 31;
        int d = d0 + c2 * 2;
        float2 a = *reinterpret_cast<const float2*>(conv_b + d);
        #pragma unroll
        for (int k = 0; k < DCONV; k++) {
            uint xu = xc2[tok + k][c2];
            float2 xf = __half22float2(*reinterpret_cast<__half2*>(&xu));
            a.x = fmaf(conv_w[d * DCONV + k],       xf.x, a.x);
            a.y = fmaf(conv_w[(d + 1) * DCONV + k], xf.y, a.y);
        }
        uint zu = *reinterpret_cast<const uint*>(
            xz + (size_t)(t0 + tok) * (2 * DINNER) + DINNER + d);
        float2 zf = __half22float2(*reinterpret_cast<__half2*>(&zu));
        uint xsp = pack2(__float2half_rn(silu_f(a.x)),
                         __float2half_rn(silu_f(a.y)));
        *reinterpret_cast<uint*>(xsh + (size_t)(t0 + tok) * DINNER + d) = xsp;
        sxu[c2][tok] = xsp;
        sgu[c2][tok] = pack2(__float2half_rn(silu_f(zf.x)),
                             __float2half_rn(silu_f(zf.y)));
    }
    __syncthreads();

    #pragma unroll
    for (int it = 0; it < 4; it++) {
        int lin = it * 256 + tid;
        int ch = lin >> 4, tp = (lin & 15) * 2;
        int r = ch >> 1;
        uint sel = (ch & 1) ? 0x7632u : 0x5410u;
        uint xa = sxu[r][tp], xb = sxu[r][tp + 1];
        uint ga = sgu[r][tp], gb = sgu[r][tp + 1];
        size_t o = (size_t)(d0 + ch) * NTOK + t0 + tp;
        *reinterpret_cast<uint*>(xsT + o) = __byte_perm(xa, xb, sel);
        *reinterpret_cast<uint*>(gT + o)  = __byte_perm(ga, gb, sel);
    }
}

// ---------------------------------------------------------------------------
// split-K reduce for x_proj
// ---------------------------------------------------------------------------
__global__ __launch_bounds__(256) void reduce_xproj(
    const float* __restrict__ part,
    f16* __restrict__ xdh,
    float* __restrict__ bcT)
{
    int idx = blockIdx.x * 256 + threadIdx.x;
    if (idx >= NTOK * XPROJ_N) return;
    float s = 0.f;
    #pragma unroll
    for (int z = 0; z < XSPLIT; z++) s += part[(size_t)z * NTOK * XPROJ_N + idx];
    xdh[idx] = __float2half_rn(s);
    int row = idx / XPROJ_N, col = idx - row * XPROJ_N;
    if (col >= DTRANK)
        bcT[(size_t)(col - DTRANK) * NTOK + row] = s;
}

// ---------------------------------------------------------------------------
// selective scan + gate; writes token-major yh directly (fused transpose).
// Block owns 16 consecutive channels (same batch); smem tile [64 tok][16 ch],
// flushed every 64 timesteps as uint2 (4 halfs) per thread.
// ---------------------------------------------------------------------------
__global__ __launch_bounds__(256) void scan_kernel(
    const f16* __restrict__ dtT, const f16* __restrict__ xsT,
    const float* __restrict__ bcT, const f16* __restrict__ gT,
    const float* __restrict__ A_log, const float* __restrict__ Dp,
    f16* __restrict__ yh)
{
    __shared__ f16 ybuf[64][18];

    int warp = threadIdx.x >> 5;
    int lane = threadIdx.x & 31;
    int chLocal = warp * 2 + (lane >> 4);        // 0..15
    int chBase = blockIdx.x * 16;                // 0..4080 (batch*channel)
    int ch = chBase + chLocal;
    int b = ch >> 11;
    int d = ch & 2047;
    int n = lane & 15;
    int rowBase = b * SEQ;
    const int dBase = chBase & (DINNER - 1);     // channel-only base for yh

    const f16* dtp = dtT + (size_t)d * NTOK + rowBase;
    const f16* xsp = xsT + (size_t)d * NTOK + rowBase;
    const f16* gp  = gT  + (size_t)d * NTOK + rowBase;
    const float* Bp = bcT + (size_t)n * NTOK + rowBase;
    const float* Cp = bcT + (size_t)(DSTATE + n) * NTOK + rowBase;

    float a  = -expf(A_log[d * DSTATE + n]);
    float Dv = Dp[d];
    float s = 0.f;

    uint2 dtu = *reinterpret_cast<const uint2*>(dtp);
    uint2 xsu = *reinterpret_cast<const uint2*>(xsp);
    uint2 gu  = *reinterpret_cast<const uint2*>(gp);
    float4 B4 = *reinterpret_cast<const float4*>(Bp);
    float4 C4 = *reinterpret_cast<const float4*>(Cp);

    const int tid = threadIdx.x;

    for (int t = 0; t < SEQ; t += 4) {
        uint2 ndt, nxs, ng; float4 nB, nC;
        if (t + 4 < SEQ) {
            ndt = *reinterpret_cast<const uint2*>(dtp + t + 4);
            nxs = *reinterpret_cast<const uint2*>(xsp + t + 4);
            ng  = *reinterpret_cast<const uint2*>(gp + t + 4);
            nB  = *reinterpret_cast<const float4*>(Bp + t + 4);
            nC  = *reinterpret_cast<const float4*>(Cp + t + 4);
        }
        float dtv[4], xsv[4], gv[4];
        unpack4(dtu, dtv); unpack4(xsu, xsv); unpack4(gu, gv);
        const float* Bv = &B4.x; const float* Cv = &C4.x;
        float yv[4];
        #pragma unroll
        for (int q = 0; q < 4; q++) {
            float dA = __expf(dtv[q] * a);
            s = fmaf(dA, s, dtv[q] * xsv[q] * Bv[q]);
            float p = s * Cv[q];
            p += __shfl_xor_sync(0xffffffffu, p, 8);
            p += __shfl_xor_sync(0xffffffffu, p, 4);
            p += __shfl_xor_sync(0xffffffffu, p, 2);
            p += __shfl_xor_sync(0xffffffffu, p, 1);
            yv[q] = (p + Dv * xsv[q]) * gv[q];
        }
        if (n == 0) {
            int tq = t & 63;
            ybuf[tq + 0][chLocal] = __float2half_rn(yv[0]);
            ybuf[tq + 1][chLocal] = __float2half_rn(yv[1]);
            ybuf[tq + 2][chLocal] = __float2half_rn(yv[2]);
            ybuf[tq + 3][chLocal] = __float2half_rn(yv[3]);
        }
        if ((t & 63) == 60) {
            __syncthreads();
            int tbase = t & ~63;
            int tok = tid >> 2, c4 = (tid & 3) * 4;
            uint2 v;
            v.x = pack2(ybuf[tok][c4 + 0], ybuf[tok][c4 + 1]);
            v.y = pack2(ybuf[tok][c4 + 2], ybuf[tok][c4 + 3]);
            *reinterpret_cast<uint2*>(
                yh + (size_t)(rowBase + tbase + tok) * DINNER + dBase + c4) = v;
            __syncthreads();
        }
        dtu = ndt; xsu = nxs; gu = ng; B4 = nB; C4 = nC;
    }
}

// ---------------------------------------------------------------------------
// Launch
// ---------------------------------------------------------------------------
extern "C" void kernel_launch(void* const* d_in, const int* in_sizes, int n_in,
                              void* d_out, int out_size)
{
    const float* x         = (const float*)d_in[0];
    const float* norm_w    = (const float*)d_in[1];
    const float* in_proj_w = (const float*)d_in[2];
    const float* conv_w    = (const float*)d_in[3];
    const float* conv_b    = (const float*)d_in[4];
    const float* x_proj_w  = (const float*)d_in[5];
    const float* dt_proj_w = (const float*)d_in[6];
    const float* dt_proj_b = (const float*)d_in[7];
    const float* A_log     = (const float*)d_in[8];
    const float* Dp        = (const float*)d_in[9];
    const float* out_proj_w= (const float*)d_in[10];
    float* out = (float*)d_out;

    float *pbcT, *ppart;
    f16 *pwi, *pwx, *pwd, *pwo, *phh, *pxz, *pxsh, *pxsT, *pgT, *pdtT,
        *pxdh, *pyh;
    cudaGetSymbolAddress((void**)&pbcT, g_bcT);
    cudaGetSymbolAddress((void**)&ppart,g_part);
    cudaGetSymbolAddress((void**)&pwi,  g_wi);
    cudaGetSymbolAddress((void**)&pwx,  g_wx);
    cudaGetSymbolAddress((void**)&pwd,  g_wd);
    cudaGetSymbolAddress((void**)&pwo,  g_wo);
    cudaGetSymbolAddress((void**)&phh,  g_hh);
    cudaGetSymbolAddress((void**)&pxz,  g_xz);
    cudaGetSymbolAddress((void**)&pxsh, g_xsh);
    cudaGetSymbolAddress((void**)&pxsT, g_xsT);
    cudaGetSymbolAddress((void**)&pgT,  g_gT);
    cudaGetSymbolAddress((void**)&pdtT, g_dtT);
    cudaGetSymbolAddress((void**)&pxdh, g_xdh);
    cudaGetSymbolAddress((void**)&pyh,  g_yh);

    cudaFuncSetAttribute(mma_gemm<0,0,0>, cudaFuncAttributeMaxDynamicSharedMemorySize, GEMM_SMEM);
    cudaFuncSetAttribute(mma_gemm<0,0,1>, cudaFuncAttributeMaxDynamicSharedMemorySize, GEMM_SMEM);
    cudaFuncSetAttribute(mma_gemm<1,1,1>, cudaFuncAttributeMaxDynamicSharedMemorySize, GEMM_SMEM);
    cudaFuncSetAttribute(mma_gemm<2,0,0>, cudaFuncAttributeMaxDynamicSharedMemorySize, GEMM_SMEM);

    // 0) all weight conversions in one launch
    convert_all<<<(NWTOT + 255) / 256, 256>>>(
        in_proj_w, pwi, x_proj_w, pwx, dt_proj_w, pwd, out_proj_w, pwo);

    // 1) RMSNorm
    rmsnorm_kernel<<<NTOK, 256>>>(x, norm_w, phh);

    // 2) in_proj -> xz fp16
    {
        dim3 grid((2 * DINNER) / 128, NTOK / 128, 1);
        mma_gemm<0,0,1><<<grid, 256, GEMM_SMEM>>>(
            phh, DMODEL, pwi, DMODEL,
            pxz, 2 * DINNER, 2 * DINNER, DMODEL, 0, nullptr, nullptr, 0);
    }

    // 3) conv + silu
    {
        dim3 grid(DINNER / CD, NTOK / CT);
        conv_silu_kernel<<<grid, 256>>>(pxz, conv_w, conv_b,
                                        pxsh, pxsT, pgT);
    }

    // 4) x_proj split-K -> fp32 partials
    {
        dim3 grid(1, NTOK / 128, XSPLIT);
        mma_gemm<0,0,0><<<grid, 256, GEMM_SMEM>>>(
            pxsh, DINNER, pwx, DINNER,
            ppart, XPROJ_N, XPROJ_N, DINNER / XSPLIT,
            (long)NTOK * XPROJ_N, nullptr, nullptr, 0);
    }
    reduce_xproj<<<(NTOK * XPROJ_N + 255) / 256, 256>>>(ppart, pxdh, pbcT);

    // 5) dt_proj + softplus -> dtT fp16
    {
        dim3 grid(DINNER / 128, NTOK / 128, 1);
        mma_gemm<1,1,1><<<grid, 256, GEMM_SMEM>>>(
            pxdh, XPROJ_N, pwd, DTRANK,
            pdtT, NTOK, DINNER, DTRANK, 0, dt_proj_b, nullptr, 0);
    }

    // 6) scan -> yh token-major directly (fused transpose)
    scan_kernel<<<(BATCH * DINNER) / 16, 256>>>(pdtT, pxsT, pbcT, pgT,
                                                A_log, Dp, pyh);

    // 7) out_proj + residual (direct, fused epilogue)
    {
        dim3 grid(DMODEL / 128, NTOK / 128, 1);
        mma_gemm<2,0,0><<<grid, 256, GEMM_SMEM>>>(
            pyh, DINNER, pwo, DINNER,
            out, DMODEL, DMODEL, DINNER, 0, nullptr, x, DMODEL);
    }
}

// round 16
// speedup vs baseline: 1.1012x; 1.0289x over previous
#include <cuda_runtime.h>
#include <cuda_fp16.h>
#include <cstdint>
#include <math.h>

// ---------------------------------------------------------------------------
// Mamba block forward. GEMMs via mma.sync HMMA fp16 single-pass (fp32 accum).
// 128x128 CTA tiles, 8 warps (64x32), 3-stage cp.async, 2 CTAs/SM.
// Scan: fused token-major store + interleaved shfl reductions.
// ---------------------------------------------------------------------------

#define BATCH   2
#define SEQ     1024
#define DMODEL  1024
#define DINNER  2048
#define DSTATE  16
#define DTRANK  64
#define DCONV   4
#define NTOK    (BATCH * SEQ)
#define XPROJ_N (DTRANK + 2 * DSTATE)   // 96
#define XSPLIT  16

typedef __half f16;

// fp32 scratch
__device__ __align__(256) float g_bcT[2 * DSTATE * NTOK];
__device__ __align__(256) float g_part[XSPLIT * NTOK * XPROJ_N];

// fp16 weights + activations
__device__ __align__(256) f16 g_wi[2 * DINNER * DMODEL];
__device__ __align__(256) f16 g_wx[XPROJ_N * DINNER];
__device__ __align__(256) f16 g_wd[DINNER * DTRANK];
__device__ __align__(256) f16 g_wo[DMODEL * DINNER];
__device__ __align__(256) f16 g_hh[NTOK * DMODEL];
__device__ __align__(256) f16 g_xz[NTOK * 2 * DINNER];
__device__ __align__(256) f16 g_xsh[NTOK * DINNER];
__device__ __align__(256) f16 g_xsT[DINNER * NTOK];
__device__ __align__(256) f16 g_gT[DINNER * NTOK];
__device__ __align__(256) f16 g_dtT[DINNER * NTOK];
__device__ __align__(256) f16 g_xdh[NTOK * XPROJ_N];
__device__ __align__(256) f16 g_yh[NTOK * DINNER];

// ---------------------------------------------------------------------------
// helpers
// ---------------------------------------------------------------------------
__device__ __forceinline__ uint32_t smem_u32(const void* p) {
    uint32_t a;
    asm("{ .reg .u64 t; cvta.to.shared.u64 t, %1; cvt.u32.u64 %0, t; }"
        : "=r"(a) : "l"(p));
    return a;
}
__device__ __forceinline__ void ldm_x4(uint32_t& r0, uint32_t& r1,
                                       uint32_t& r2, uint32_t& r3, uint32_t a) {
    asm volatile("ldmatrix.sync.aligned.m8n8.x4.shared.b16 {%0,%1,%2,%3}, [%4];"
                 : "=r"(r0), "=r"(r1), "=r"(r2), "=r"(r3) : "r"(a));
}
__device__ __forceinline__ void mma16816(float* d, const uint32_t* a,
                                         const uint32_t* b) {
    asm volatile(
        "mma.sync.aligned.m16n8k16.row.col.f32.f16.f16.f32 "
        "{%0,%1,%2,%3}, {%4,%5,%6,%7}, {%8,%9}, {%0,%1,%2,%3};"
        : "+f"(d[0]), "+f"(d[1]), "+f"(d[2]), "+f"(d[3])
        : "r"(a[0]), "r"(a[1]), "r"(a[2]), "r"(a[3]), "r"(b[0]), "r"(b[1]));
}
__device__ __forceinline__ void cp16(uint32_t dst, const void* src, int sz) {
    asm volatile("cp.async.cg.shared.global [%0], [%1], 16, %2;"
                 :: "r"(dst), "l"(src), "r"(sz) : "memory");
}
#define CP_COMMIT() asm volatile("cp.async.commit_group;" ::: "memory")
#define CP_WAIT(n)  asm volatile("cp.async.wait_group %0;" :: "n"(n) : "memory")

__device__ __forceinline__ uint32_t pack2(f16 a, f16 b) {
    return ((uint32_t)__half_as_ushort(b) << 16) | __half_as_ushort(a);
}
__device__ __forceinline__ uint2 cvt4(float4 v) {
    uint2 r;
    r.x = pack2(__float2half_rn(v.x), __float2half_rn(v.y));
    r.y = pack2(__float2half_rn(v.z), __float2half_rn(v.w));
    return r;
}
__device__ __forceinline__ void unpack4(uint2 u, float* f) {
    __half2 a = *reinterpret_cast<__half2*>(&u.x);
    __half2 b = *reinterpret_cast<__half2*>(&u.y);
    float2 fa = __half22float2(a), fb = __half22float2(b);
    f[0] = fa.x; f[1] = fa.y; f[2] = fb.x; f[3] = fb.y;
}
__device__ __forceinline__ float softplus_f(float v) {
    return (v > 15.f) ? v : log1pf(__expf(v));
}
__device__ __forceinline__ float silu_f(float v) {
    return v / (1.f + __expf(-v));
}

// ---------------------------------------------------------------------------
// HMMA GEMM (NT): C[M,N] = A[M,K]·B[N,K]^T, fp16 x fp16 -> fp32 accum.
// CTA 128x128, 8 warps (64x32), K-chunk 64, 3-stage cp.async, 2 CTAs/SM.
// One __syncthreads per chunk (loadStage issued post-barrier).
// EPI: 0 none, 1 softplus(acc+bias[n]), 2 acc+res[m,n] (fp32 out).
// TRANS: transposed fp16 store.  HOUT: 1 fp16 out, else fp32 (+split-K).
// ---------------------------------------------------------------------------
#define STAGE_SZ 32768
#define NSTAGE 3
#define GEMM_SMEM (NSTAGE * STAGE_SZ)   // 96 KB

template<int EPI, int TRANS, int HOUT>
__global__ void __launch_bounds__(256, 2) mma_gemm(
    const f16* __restrict__ A, int lda,
    const f16* __restrict__ B, int ldb,
    void* __restrict__ Cv, int ldc, int N, int Ksplit, long partStride,
    const float* __restrict__ bias,
    const float* __restrict__ res, int ldres)
{
    extern __shared__ char smem[];
    const uint32_t sb = smem_u32(smem);
    const int tid = threadIdx.x;
    const int bRow = blockIdx.y * 128, bCol = blockIdx.x * 128;
    const int kbase = blockIdx.z * Ksplit;
    const int nChunks = Ksplit >> 6;

    const int wid = tid >> 5, l = tid & 31;
    const int wm = (wid >> 2) * 64, wn = (wid & 3) * 32;

    float acc[4][4][4];
    #pragma unroll
    for (int a = 0; a < 4; a++)
        #pragma unroll
        for (int b = 0; b < 4; b++)
            #pragma unroll
            for (int c = 0; c < 4; c++) acc[a][b][c] = 0.f;

    auto loadStage = [&](int c) {
        const int kt = kbase + (c << 6);
        const uint32_t base = sb + (c % NSTAGE) * STAGE_SZ;
        #pragma unroll
        for (int it = 0; it < 4; it++) {
            int lin = it * 256 + tid;
            int row = lin >> 3, ch = lin & 7;
            uint32_t d = base + row * 128 + (((ch ^ (row & 7)) << 4));
            size_t aoff = (size_t)(bRow + row) * lda + kt + ch * 8;
            cp16(d, A + aoff, 16);
            int bn = bCol + row;
            int ok = (bn < N) ? 16 : 0;
            size_t boff = (size_t)(bn < N ? bn : 0) * ldb + kt + ch * 8;
            cp16(d + 16384, B + boff, ok);
        }
        CP_COMMIT();
    };

    loadStage(0);
    if (nChunks > 1) loadStage(1);
    for (int c = 0; c < nChunks; c++) {
        if (c + 1 < nChunks) { CP_WAIT(1); }
        else                 { CP_WAIT(0); }
        __syncthreads();
        if (c + 2 < nChunks) loadStage(c + 2);

        const uint32_t st = sb + (c % NSTAGE) * STAGE_SZ;
        const int hkA = l >> 4;
        const int matb = l >> 3;
        const int rB0 = wn + (l & 7) + ((matb >> 1) << 3);
        const int hkB = matb & 1;

        #pragma unroll
        for (int ks = 0; ks < 4; ks++) {
            uint32_t Af[4][4], Bf[4][2];
            #pragma unroll
            for (int mi = 0; mi < 4; mi++) {
                int r = wm + mi * 16 + (l & 15);
                int ck = 2 * ks + hkA;
                uint32_t ad = st + r * 128 + ((ck ^ (r & 7)) << 4);
                ldm_x4(Af[mi][0], Af[mi][1], Af[mi][2], Af[mi][3], ad);
            }
            #pragma unroll
            for (int ng = 0; ng < 2; ng++) {
                int r = rB0 + ng * 16;
                int ck = 2 * ks + hkB;
                uint32_t ad = st + 16384 + r * 128 + ((ck ^ (r & 7)) << 4);
                uint32_t t0, t1, t2, t3;
                ldm_x4(t0, t1, t2, t3, ad);
                Bf[ng*2][0] = t0; Bf[ng*2][1] = t1;
                Bf[ng*2+1][0] = t2; Bf[ng*2+1][1] = t3;
            }
            #pragma unroll
            for (int mi = 0; mi < 4; mi++)
                #pragma unroll
                for (int ni = 0; ni < 4; ni++)
                    mma16816(acc[mi][ni], Af[mi], Bf[ni]);
        }
    }

    if (TRANS) {
        __syncthreads();
        float* ts = reinterpret_cast<float*>(smem);   // [128][132]
        #pragma unroll
        for (int mi = 0; mi < 4; mi++) {
            #pragma unroll
            for (int h2 = 0; h2 < 2; h2++) {
                int row = wm + mi * 16 + h2 * 8 + (l >> 2);
                #pragma unroll
                for (int ni = 0; ni < 4; ni++) {
                    int col = wn + ni * 8 + (l & 3) * 2;
                    float v0 = acc[mi][ni][h2 * 2 + 0];
                    float v1 = acc[mi][ni][h2 * 2 + 1];
                    if (EPI == 1) {
                        v0 = softplus_f(v0 + bias[bCol + col]);
                        v1 = softplus_f(v1 + bias[bCol + col + 1]);
                    }
                    ts[(col) * 132 + row] = v0;
                    ts[(col + 1) * 132 + row] = v1;
                }
            }
        }
        __syncthreads();
        f16* Ch = reinterpret_cast<f16*>(Cv);
        #pragma unroll
        for (int i = 0; i < 32; i++) {
            int idx = i * 256 + tid;
            int r = idx >> 6, c2 = (idx & 63) * 2;
            uint v = pack2(__float2half_rn(ts[r * 132 + c2]),
                           __float2half_rn(ts[r * 132 + c2 + 1]));
            *reinterpret_cast<uint*>(Ch + (size_t)(bCol + r) * ldc + bRow + c2) = v;
        }
    } else {
        #pragma unroll
        for (int mi = 0; mi < 4; mi++) {
            #pragma unroll
            for (int h2 = 0; h2 < 2; h2++) {
                int row = bRow + wm + mi * 16 + h2 * 8 + (l >> 2);
                #pragma unroll
                for (int ni = 0; ni < 4; ni++) {
                    int col = bCol + wn + ni * 8 + (l & 3) * 2;
                    if (col < N) {
                        float v0 = acc[mi][ni][h2 * 2 + 0];
                        float v1 = acc[mi][ni][h2 * 2 + 1];
                        if (EPI == 1) {
                            v0 = softplus_f(v0 + bias[col]);
                            v1 = softplus_f(v1 + bias[col + 1]);
                        } else if (EPI == 2) {
                            const float* rr = res + (size_t)row * ldres + col;
                            v0 += rr[0]; v1 += rr[1];
                        }
                        if (HOUT) {
                            f16* Ch = reinterpret_cast<f16*>(Cv);
                            *reinterpret_cast<uint*>(
                                Ch + (size_t)row * ldc + col) =
                                pack2(__float2half_rn(v0), __float2half_rn(v1));
                        } else {
                            float* Cf = reinterpret_cast<float*>(Cv) +
                                        (long)blockIdx.z * partStride;
                            *reinterpret_cast<float2*>(
                                Cf + (size_t)row * ldc + col) =
                                make_float2(v0, v1);
                        }
                    }
                }
            }
        }
    }
}

// ---------------------------------------------------------------------------
// fused: all weight fp32->fp16 conversions + rmsnorm, one launch.
// blocks [0, NTOK): rmsnorm; blocks [NTOK, NTOK+NWB): converts.
// ---------------------------------------------------------------------------
#define NW0 (2 * DINNER * DMODEL / 4)
#define NW1 (XPROJ_N * DINNER / 4)
#define NW2 (DINNER * DTRANK / 4)
#define NW3 (DMODEL * DINNER / 4)
#define NWTOT (NW0 + NW1 + NW2 + NW3)
#define NWB ((NWTOT + 255) / 256)

__global__ __launch_bounds__(256) void prep_kernel(
    const float* __restrict__ x, const float* __restrict__ norm_w,
    f16* __restrict__ hh,
    const float* __restrict__ w0, f16* __restrict__ o0,
    const float* __restrict__ w1, f16* __restrict__ o1,
    const float* __restrict__ w2, f16* __restrict__ o2,
    const float* __restrict__ w3, f16* __restrict__ o3)
{
    int tid = threadIdx.x;
    if (blockIdx.x < NTOK) {
        // rmsnorm
        int row = blockIdx.x;
        float4 v = reinterpret_cast<const float4*>(x + (size_t)row * DMODEL)[tid];
        float ss = v.x * v.x + v.y * v.y + v.z * v.z + v.w * v.w;
        __shared__ float red[8];
        #pragma unroll
        for (int o = 16; o > 0; o >>= 1) ss += __shfl_xor_sync(0xffffffffu, ss, o);
        if ((tid & 31) == 0) red[tid >> 5] = ss;
        __syncthreads();
        if (tid < 32) {
            float t = (tid < 8) ? red[tid] : 0.f;
            #pragma unroll
            for (int o = 4; o > 0; o >>= 1) t += __shfl_xor_sync(0xffffffffu, t, o);
            if (tid == 0) red[0] = t;
        }
        __syncthreads();
        float scale = rsqrtf(red[0] * (1.0f / DMODEL) + 1e-5f);
        float4 wv = reinterpret_cast<const float4*>(norm_w)[tid];
        float4 o;
        o.x = v.x * scale * wv.x;  o.y = v.y * scale * wv.y;
        o.z = v.z * scale * wv.z;  o.w = v.w * scale * wv.w;
        reinterpret_cast<uint2*>(hh + (size_t)row * DMODEL)[tid] = cvt4(o);
    } else {
        int i = (blockIdx.x - NTOK) * 256 + tid;
        const float* w; f16* o; int j;
        if (i < NW0)                  { w = w0; o = o0; j = i; }
        else if (i < NW0 + NW1)       { w = w1; o = o1; j = i - NW0; }
        else if (i < NW0 + NW1 + NW2) { w = w2; o = o2; j = i - NW0 - NW1; }
        else if (i < NWTOT)           { w = w3; o = o3; j = i - NW0 - NW1 - NW2; }
        else return;
        float4 v = reinterpret_cast<const float4*>(w)[j];
        reinterpret_cast<uint2*>(o)[j] = cvt4(v);
    }
}

// ---------------------------------------------------------------------------
// Tiled conv(width4)+SiLU + silu(z), half2-vectorized, packed smem.
// ---------------------------------------------------------------------------
#define CT 32
#define CD 64

__global__ __launch_bounds__(256) void conv_silu_kernel(
    const f16* __restrict__ xz,
    const float* __restrict__ conv_w, const float* __restrict__ conv_b,
    f16* __restrict__ xsh, f16* __restrict__ xsT, f16* __restrict__ gT)
{
    __shared__ uint xc2[CT + 3][CD / 2];
    __shared__ uint sxu[CD / 2][CT + 1];
    __shared__ uint sgu[CD / 2][CT + 1];

    const int tid = threadIdx.x;
    const int d0 = blockIdx.x * CD;
    const int t0 = blockIdx.y * CT;
    const bool halo = (t0 & (SEQ - 1)) != 0;

    #pragma unroll
    for (int it = 0; it < 5; it++) {
        int lin = it * 256 + tid;
        if (lin < (CT + 3) * (CD / 2)) {
            int i = lin >> 5, c2 = lin & 31;
            uint v = 0;
            if (i >= 3 || halo)
                v = *reinterpret_cast<const uint*>(
                    xz + (size_t)(t0 - 3 + i) * (2 * DINNER) + d0 + c2 * 2);
            xc2[i][c2] = v;
        }
    }
    __syncthreads();

    #pragma unroll
    for (int it = 0; it < 4; it++) {
        int lin = it * 256 + tid;
        int tok = lin >> 5, c2 = lin & 31;
        int d = d0 + c2 * 2;
        float2 a = *reinterpret_cast<const float2*>(conv_b + d);
        #pragma unroll
        for (int k = 0; k < DCONV; k++) {
            uint xu = xc2[tok + k][c2];
            float2 xf = __half22float2(*reinterpret_cast<__half2*>(&xu));
            a.x = fmaf(conv_w[d * DCONV + k],       xf.x, a.x);
            a.y = fmaf(conv_w[(d + 1) * DCONV + k], xf.y, a.y);
        }
        uint zu = *reinterpret_cast<const uint*>(
            xz + (size_t)(t0 + tok) * (2 * DINNER) + DINNER + d);
        float2 zf = __half22float2(*reinterpret_cast<__half2*>(&zu));
        uint xsp = pack2(__float2half_rn(silu_f(a.x)),
                         __float2half_rn(silu_f(a.y)));
        *reinterpret_cast<uint*>(xsh + (size_t)(t0 + tok) * DINNER + d) = xsp;
        sxu[c2][tok] = xsp;
        sgu[c2][tok] = pack2(__float2half_rn(silu_f(zf.x)),
                             __float2half_rn(silu_f(zf.y)));
    }
    __syncthreads();

    #pragma unroll
    for (int it = 0; it < 4; it++) {
        int lin = it * 256 + tid;
        int ch = lin >> 4, tp = (lin & 15) * 2;
        int r = ch >> 1;
        uint sel = (ch & 1) ? 0x7632u : 0x5410u;
        uint xa = sxu[r][tp], xb = sxu[r][tp + 1];
        uint ga = sgu[r][tp], gb = sgu[r][tp + 1];
        size_t o = (size_t)(d0 + ch) * NTOK + t0 + tp;
        *reinterpret_cast<uint*>(xsT + o) = __byte_perm(xa, xb, sel);
        *reinterpret_cast<uint*>(gT + o)  = __byte_perm(ga, gb, sel);
    }
}

// ---------------------------------------------------------------------------
// split-K reduce for x_proj
// ---------------------------------------------------------------------------
__global__ __launch_bounds__(256) void reduce_xproj(
    const float* __restrict__ part,
    f16* __restrict__ xdh,
    float* __restrict__ bcT)
{
    int idx = blockIdx.x * 256 + threadIdx.x;
    if (idx >= NTOK * XPROJ_N) return;
    float s = 0.f;
    #pragma unroll
    for (int z = 0; z < XSPLIT; z++) s += part[(size_t)z * NTOK * XPROJ_N + idx];
    xdh[idx] = __float2half_rn(s);
    int row = idx / XPROJ_N, col = idx - row * XPROJ_N;
    if (col >= DTRANK)
        bcT[(size_t)(col - DTRANK) * NTOK + row] = s;
}

// ---------------------------------------------------------------------------
// selective scan + gate; token-major yh store (fused transpose), and
// interleaved 4-way butterfly reductions for shfl ILP.
// ---------------------------------------------------------------------------
__global__ __launch_bounds__(256) void scan_kernel(
    const f16* __restrict__ dtT, const f16* __restrict__ xsT,
    const float* __restrict__ bcT, const f16* __restrict__ gT,
    const float* __restrict__ A_log, const float* __restrict__ Dp,
    f16* __restrict__ yh)
{
    __shared__ f16 ybuf[64][18];

    int warp = threadIdx.x >> 5;
    int lane = threadIdx.x & 31;
    int chLocal = warp * 2 + (lane >> 4);
    int chBase = blockIdx.x * 16;
    int ch = chBase + chLocal;
    int b = ch >> 11;
    int d = ch & 2047;
    int n = lane & 15;
    int rowBase = b * SEQ;
    const int dBase = chBase & (DINNER - 1);

    const f16* dtp = dtT + (size_t)d * NTOK + rowBase;
    const f16* xsp = xsT + (size_t)d * NTOK + rowBase;
    const f16* gp  = gT  + (size_t)d * NTOK + rowBase;
    const float* Bp = bcT + (size_t)n * NTOK + rowBase;
    const float* Cp = bcT + (size_t)(DSTATE + n) * NTOK + rowBase;

    float a  = -expf(A_log[d * DSTATE + n]);
    float Dv = Dp[d];
    float s = 0.f;

    uint2 dtu = *reinterpret_cast<const uint2*>(dtp);
    uint2 xsu = *reinterpret_cast<const uint2*>(xsp);
    uint2 gu  = *reinterpret_cast<const uint2*>(gp);
    float4 B4 = *reinterpret_cast<const float4*>(Bp);
    float4 C4 = *reinterpret_cast<const float4*>(Cp);

    const int tid = threadIdx.x;

    for (int t = 0; t < SEQ; t += 4) {
        uint2 ndt, nxs, ng; float4 nB, nC;
        if (t + 4 < SEQ) {
            ndt = *reinterpret_cast<const uint2*>(dtp + t + 4);
            nxs = *reinterpret_cast<const uint2*>(xsp + t + 4);
            ng  = *reinterpret_cast<const uint2*>(gp + t + 4);
            nB  = *reinterpret_cast<const float4*>(Bp + t + 4);
            nC  = *reinterpret_cast<const float4*>(Cp + t + 4);
        }
        float dtv[4], xsv[4], gv[4];
        unpack4(dtu, dtv); unpack4(xsu, xsv); unpack4(gu, gv);
        const float* Bv = &B4.x; const float* Cv = &C4.x;

        // recurrence (serial) — collect p[q]
        float p[4];
        #pragma unroll
        for (int q = 0; q < 4; q++) {
            float dA = __expf(dtv[q] * a);
            s = fmaf(dA, s, dtv[q] * xsv[q] * Bv[q]);
            p[q] = s * Cv[q];
        }
        // 4 interleaved butterflies (ILP over q; same per-q fp32 order)
        #pragma unroll
        for (int o = 8; o > 0; o >>= 1) {
            #pragma unroll
            for (int q = 0; q < 4; q++)
                p[q] += __shfl_xor_sync(0xffffffffu, p[q], o);
        }
        if (n == 0) {
            int tq = t & 63;
            #pragma unroll
            for (int q = 0; q < 4; q++)
                ybuf[tq + q][chLocal] =
                    __float2half_rn((p[q] + Dv * xsv[q]) * gv[q]);
        }
        if ((t & 63) == 60) {
            __syncthreads();
            int tbase = t & ~63;
            int tok = tid >> 2, c4 = (tid & 3) * 4;
            uint2 v;
            v.x = pack2(ybuf[tok][c4 + 0], ybuf[tok][c4 + 1]);
            v.y = pack2(ybuf[tok][c4 + 2], ybuf[tok][c4 + 3]);
            *reinterpret_cast<uint2*>(
                yh + (size_t)(rowBase + tbase + tok) * DINNER + dBase + c4) = v;
            __syncthreads();
        }
        dtu = ndt; xsu = nxs; gu = ng; B4 = nB; C4 = nC;
    }
}

// ---------------------------------------------------------------------------
// Launch
// ---------------------------------------------------------------------------
extern "C" void kernel_launch(void* const* d_in, const int* in_sizes, int n_in,
                              void* d_out, int out_size)
{
    const float* x         = (const float*)d_in[0];
    const float* norm_w    = (const float*)d_in[1];
    const float* in_proj_w = (const float*)d_in[2];
    const float* conv_w    = (const float*)d_in[3];
    const float* conv_b    = (const float*)d_in[4];
    const float* x_proj_w  = (const float*)d_in[5];
    const float* dt_proj_w = (const float*)d_in[6];
    const float* dt_proj_b = (const float*)d_in[7];
    const float* A_log     = (const float*)d_in[8];
    const float* Dp        = (const float*)d_in[9];
    const float* out_proj_w= (const float*)d_in[10];
    float* out = (float*)d_out;

    float *pbcT, *ppart;
    f16 *pwi, *pwx, *pwd, *pwo, *phh, *pxz, *pxsh, *pxsT, *pgT, *pdtT,
        *pxdh, *pyh;
    cudaGetSymbolAddress((void**)&pbcT, g_bcT);
    cudaGetSymbolAddress((void**)&ppart,g_part);
    cudaGetSymbolAddress((void**)&pwi,  g_wi);
    cudaGetSymbolAddress((void**)&pwx,  g_wx);
    cudaGetSymbolAddress((void**)&pwd,  g_wd);
    cudaGetSymbolAddress((void**)&pwo,  g_wo);
    cudaGetSymbolAddress((void**)&phh,  g_hh);
    cudaGetSymbolAddress((void**)&pxz,  g_xz);
    cudaGetSymbolAddress((void**)&pxsh, g_xsh);
    cudaGetSymbolAddress((void**)&pxsT, g_xsT);
    cudaGetSymbolAddress((void**)&pgT,  g_gT);
    cudaGetSymbolAddress((void**)&pdtT, g_dtT);
    cudaGetSymbolAddress((void**)&pxdh, g_xdh);
    cudaGetSymbolAddress((void**)&pyh,  g_yh);

    cudaFuncSetAttribute(mma_gemm<0,0,0>, cudaFuncAttributeMaxDynamicSharedMemorySize, GEMM_SMEM);
    cudaFuncSetAttribute(mma_gemm<0,0,1>, cudaFuncAttributeMaxDynamicSharedMemorySize, GEMM_SMEM);
    cudaFuncSetAttribute(mma_gemm<1,1,1>, cudaFuncAttributeMaxDynamicSharedMemorySize, GEMM_SMEM);
    cudaFuncSetAttribute(mma_gemm<2,0,0>, cudaFuncAttributeMaxDynamicSharedMemorySize, GEMM_SMEM);

    // 0) fused weight conversion + rmsnorm
    prep_kernel<<<NTOK + NWB, 256>>>(x, norm_w, phh,
                                     in_proj_w, pwi, x_proj_w, pwx,
                                     dt_proj_w, pwd, out_proj_w, pwo);

    // 1) in_proj -> xz fp16
    {
        dim3 grid((2 * DINNER) / 128, NTOK / 128, 1);
        mma_gemm<0,0,1><<<grid, 256, GEMM_SMEM>>>(
            phh, DMODEL, pwi, DMODEL,
            pxz, 2 * DINNER, 2 * DINNER, DMODEL, 0, nullptr, nullptr, 0);
    }

    // 2) conv + silu
    {
        dim3 grid(DINNER / CD, NTOK / CT);
        conv_silu_kernel<<<grid, 256>>>(pxz, conv_w, conv_b,
                                        pxsh, pxsT, pgT);
    }

    // 3) x_proj split-K -> fp32 partials
    {
        dim3 grid(1, NTOK / 128, XSPLIT);
        mma_gemm<0,0,0><<<grid, 256, GEMM_SMEM>>>(
            pxsh, DINNER, pwx, DINNER,
            ppart, XPROJ_N, XPROJ_N, DINNER / XSPLIT,
            (long)NTOK * XPROJ_N, nullptr, nullptr, 0);
    }
    reduce_xproj<<<(NTOK * XPROJ_N + 255) / 256, 256>>>(ppart, pxdh, pbcT);

    // 4) dt_proj + softplus -> dtT fp16
    {
        dim3 grid(DINNER / 128, NTOK / 128, 1);
        mma_gemm<1,1,1><<<grid, 256, GEMM_SMEM>>>(
            pxdh, XPROJ_N, pwd, DTRANK,
            pdtT, NTOK, DINNER, DTRANK, 0, dt_proj_b, nullptr, 0);
    }

    // 5) scan -> yh token-major
    scan_kernel<<<(BATCH * DINNER) / 16, 256>>>(pdtT, pxsT, pbcT, pgT,
                                                A_log, Dp, pyh);

    // 6) out_proj + residual
    {
        dim3 grid(DMODEL / 128, NTOK / 128, 1);
        mma_gemm<2,0,0><<<grid, 256, GEMM_SMEM>>>(
            pyh, DINNER, pwo, DINNER,
            out, DMODEL, DMODEL, DINNER, 0, nullptr, x, DMODEL);
    }
}